// round 5
// baseline (speedup 1.0000x reference)
#include <cuda_runtime.h>

// Problem constants
#define BB   4
#define CC   256     // output channels (C)
#define CI   128     // inner attention dim
#define NN   4096    // H*W pixels

// Scratch (static __device__ — no allocation allowed)
__device__ float g_q[BB * NN * CI];   // [b][n][ci]
__device__ float g_k[BB * CI * NN];   // [b][ci][m]  (transposed for S-phase)
__device__ float g_v[BB * NN * CC];   // [b][m][c]

// ---------------------------------------------------------------------------
// Packed fp32x2 helpers (FFMA2 path — only reachable via PTX f32x2 ops)
// ---------------------------------------------------------------------------
__device__ __forceinline__ unsigned long long bcast2(float x) {
    unsigned long long r;
    asm("mov.b64 %0, {%1, %1};" : "=l"(r) : "f"(x));
    return r;
}
__device__ __forceinline__ void fma2(unsigned long long& d,
                                     unsigned long long a,
                                     unsigned long long b) {
    asm("fma.rn.f32x2 %0, %1, %2, %3;" : "=l"(d) : "l"(a), "l"(b), "l"(d));
}
__device__ __forceinline__ void mul2(unsigned long long& d,
                                     unsigned long long a) {
    asm("mul.rn.f32x2 %0, %1, %2;" : "=l"(d) : "l"(d), "l"(a));
}
__device__ __forceinline__ float2 up2(unsigned long long v) {
    float2 f;
    asm("mov.b64 {%0, %1}, %2;" : "=f"(f.x), "=f"(f.y) : "l"(v));
    return f;
}

// ---------------------------------------------------------------------------
// Projection: out = W @ in + bias  (1x1 conv). in: [b][Cin][N] (n contig)
// Tile: 64 n  x 128 o.  256 threads as 16(ty) x 16(tx), micro 4n x 8o.
// ---------------------------------------------------------------------------
template <bool TRANS>
__device__ __forceinline__ void proj_body(const float* __restrict__ in,
                                          const float* __restrict__ W,
                                          const float* __restrict__ bias,
                                          float* __restrict__ out,
                                          int Cin, int O, int o0) {
    __shared__ float Xs[32 * 64];    // [cc][nn]
    __shared__ float Ws[32 * 132];   // [cc][oo], padded

    const int tid = threadIdx.x;
    const int ty = tid >> 4;
    const int tx = tid & 15;
    const int n0 = blockIdx.x * 64;
    const int b  = blockIdx.z;
    const float* inb = in + (size_t)b * Cin * NN;

    unsigned long long acc2[4][4];
#pragma unroll
    for (int i = 0; i < 4; i++)
#pragma unroll
        for (int j = 0; j < 4; j++) acc2[i][j] = 0ull;

    for (int c0 = 0; c0 < Cin; c0 += 32) {
#pragma unroll
        for (int t = 0; t < 8; t++) {          // 32*64 = 2048 elems
            int e = tid + t * 256;
            int cc = e >> 6, nn = e & 63;
            Xs[cc * 64 + nn] = inb[(size_t)(c0 + cc) * NN + n0 + nn];
        }
#pragma unroll
        for (int t = 0; t < 16; t++) {         // 128*32 = 4096 elems
            int e = tid + t * 256;
            int oo = e >> 5, cc = e & 31;
            Ws[cc * 132 + oo] = W[(size_t)(o0 + oo) * Cin + c0 + cc];
        }
        __syncthreads();

#pragma unroll 4
        for (int cc = 0; cc < 32; cc++) {
            ulonglong2 w0 = *(const ulonglong2*)&Ws[cc * 132 + tx * 4];
            ulonglong2 w1 = *(const ulonglong2*)&Ws[cc * 132 + 64 + tx * 4];
#pragma unroll
            for (int i = 0; i < 4; i++) {
                unsigned long long aa = bcast2(Xs[cc * 64 + ty * 4 + i]);
                fma2(acc2[i][0], aa, w0.x); fma2(acc2[i][1], aa, w0.y);
                fma2(acc2[i][2], aa, w1.x); fma2(acc2[i][3], aa, w1.y);
            }
        }
        __syncthreads();
    }

    // Unpack to scalar tail (same as before)
    float acc[4][8];
#pragma unroll
    for (int i = 0; i < 4; i++)
#pragma unroll
        for (int p = 0; p < 4; p++) {
            float2 f = up2(acc2[i][p]);
            acc[i][p * 2]     = f.x;
            acc[i][p * 2 + 1] = f.y;
        }

    float bj[8];
#pragma unroll
    for (int u = 0; u < 4; u++) {
        bj[u]     = bias[o0 + tx * 4 + u];
        bj[4 + u] = bias[o0 + 64 + tx * 4 + u];
    }

    if (!TRANS) {
        // out[b][n][o]
#pragma unroll
        for (int i = 0; i < 4; i++) {
            size_t base = (size_t)b * NN * O + (size_t)(n0 + ty * 4 + i) * O + o0;
            *(float4*)&out[base + tx * 4] =
                make_float4(acc[i][0] + bj[0], acc[i][1] + bj[1],
                            acc[i][2] + bj[2], acc[i][3] + bj[3]);
            *(float4*)&out[base + 64 + tx * 4] =
                make_float4(acc[i][4] + bj[4], acc[i][5] + bj[5],
                            acc[i][6] + bj[6], acc[i][7] + bj[7]);
        }
    } else {
        // out[b][o][n]
#pragma unroll
        for (int half = 0; half < 2; half++)
#pragma unroll
            for (int u = 0; u < 4; u++) {
                int o = o0 + half * 64 + tx * 4 + u;
                float bb = bj[half * 4 + u];
                *(float4*)&out[(size_t)b * O * NN + (size_t)o * NN + n0 + ty * 4] =
                    make_float4(acc[0][half * 4 + u] + bb, acc[1][half * 4 + u] + bb,
                                acc[2][half * 4 + u] + bb, acc[3][half * 4 + u] + bb);
            }
    }
}

// Single merged projection launch: blockIdx.y selects {q, k, v-half0, v-half1}
__global__ __launch_bounds__(256) void proj_all_kernel(
    const float* __restrict__ x, const float* __restrict__ z,
    const float* __restrict__ Wq, const float* __restrict__ bq,
    const float* __restrict__ Wk, const float* __restrict__ bk,
    const float* __restrict__ Wv, const float* __restrict__ bv) {
    int sel = blockIdx.y;
    if (sel == 0)
        proj_body<false>(x, Wq, bq, g_q, 256, 128, 0);
    else if (sel == 1)
        proj_body<true>(z, Wk, bk, g_k, 256, 128, 0);
    else
        proj_body<false>(z, Wv, bv, g_v, 256, 256, (sel - 2) * 128);
}

// ---------------------------------------------------------------------------
// Fused attention: per block = one batch b and 64 query rows (n0..n0+63).
// Online softmax over m chunks of 128.  O accumulator [64 n][256 c] packed f32x2.
// ---------------------------------------------------------------------------
#define QS_F  (64 * 132)
#define KS_F  (128 * 128)
#define PS_F  (64 * 132)
#define VS_F  (64 * 256)
#define ATTN_SMEM_FLOATS (QS_F + KS_F + PS_F + VS_F + 3 * 64)
#define ATTN_SMEM_BYTES  (ATTN_SMEM_FLOATS * 4)

__global__ __launch_bounds__(256, 1)
void attn_kernel(const float* __restrict__ x_main,
                 const float* __restrict__ gamma_p,
                 float* __restrict__ out) {
    extern __shared__ float smf[];
    float* Qs  = smf;                 // [64][132]
    float* Ks  = Qs + QS_F;           // [128 k][128 m]
    float* Ps  = Ks + KS_F;           // [64][132]
    float* Vs  = Ps + PS_F;           // [64 m][256 c]
    float* m_s = Vs + VS_F;
    float* l_s = m_s + 64;
    float* a_s = l_s + 64;

    const int tid = threadIdx.x;
    const int ty = tid >> 4;
    const int tx = tid & 15;
    const int n0 = blockIdx.x * 64;
    const int b  = blockIdx.y;

    const float* qg = g_q + ((size_t)b * NN + n0) * CI;
    const float* kg = g_k + (size_t)b * CI * NN;
    const float* vg = g_v + (size_t)b * NN * CC;

    // O accumulator: 4 rows x 16 cols as 4x8 packed pairs
    unsigned long long o2[4][8];
#pragma unroll
    for (int i = 0; i < 4; i++)
#pragma unroll
        for (int j = 0; j < 8; j++) o2[i][j] = 0ull;

    // Load Q tile [64][128]
#pragma unroll
    for (int t = 0; t < 32; t++) {
        int e = tid + t * 256;
        int nn = e >> 7, kk = e & 127;
        Qs[nn * 132 + kk] = qg[(size_t)nn * CI + kk];
    }
    if (tid < 64) { m_s[tid] = -1e30f; l_s[tid] = 0.f; }
    __syncthreads();

    for (int m0 = 0; m0 < NN; m0 += 128) {
        // ---- load K chunk [128 k][128 m] ----
#pragma unroll
        for (int t = 0; t < 16; t++) {
            int e = tid + t * 256;
            int kk = e >> 5, mq = (e & 31) << 2;
            *(float4*)&Ks[kk * 128 + mq] =
                *(const float4*)&kg[(size_t)kk * NN + m0 + mq];
        }
        __syncthreads();

        // ---- S = Q K^T  (micro 4n x 8m packed; cols: half*64 + tx*4 + u) ----
        unsigned long long s2[4][4];
#pragma unroll
        for (int i = 0; i < 4; i++)
#pragma unroll
            for (int j = 0; j < 4; j++) s2[i][j] = 0ull;

#pragma unroll 4
        for (int kk = 0; kk < 128; kk++) {
            ulonglong2 b0 = *(const ulonglong2*)&Ks[kk * 128 + tx * 4];
            ulonglong2 b1 = *(const ulonglong2*)&Ks[kk * 128 + 64 + tx * 4];
#pragma unroll
            for (int i = 0; i < 4; i++) {
                unsigned long long aa = bcast2(Qs[(ty * 4 + i) * 132 + kk]);
                fma2(s2[i][0], aa, b0.x); fma2(s2[i][1], aa, b0.y);
                fma2(s2[i][2], aa, b1.x); fma2(s2[i][3], aa, b1.y);
            }
        }
#pragma unroll
        for (int i = 0; i < 4; i++) {
            *(ulonglong2*)&Ps[(ty * 4 + i) * 132 + tx * 4] =
                make_ulonglong2(s2[i][0], s2[i][1]);
            *(ulonglong2*)&Ps[(ty * 4 + i) * 132 + 64 + tx * 4] =
                make_ulonglong2(s2[i][2], s2[i][3]);
        }
        __syncthreads();

        // ---- online softmax: 4 threads per row, 32 cols each ----
        {
            int r = tid >> 2, p = tid & 3;
            float* row = Ps + r * 132 + p * 32;
            float mx = -1e30f;
#pragma unroll
            for (int j = 0; j < 32; j++) mx = fmaxf(mx, row[j]);
            mx = fmaxf(mx, __shfl_xor_sync(0xffffffffu, mx, 1));
            mx = fmaxf(mx, __shfl_xor_sync(0xffffffffu, mx, 2));
            float mo = m_s[r];
            float mn = fmaxf(mo, mx);
            float sum = 0.f;
#pragma unroll
            for (int j = 0; j < 32; j++) {
                float ev = __expf(row[j] - mn);
                row[j] = ev;
                sum += ev;
            }
            sum += __shfl_xor_sync(0xffffffffu, sum, 1);
            sum += __shfl_xor_sync(0xffffffffu, sum, 2);
            if (p == 0) {
                float al = __expf(mo - mn);
                a_s[r] = al;
                l_s[r] = l_s[r] * al + sum;
                m_s[r] = mn;
            }
        }
        __syncthreads();

        // ---- rescale accumulator (packed) ----
#pragma unroll
        for (int i = 0; i < 4; i++) {
            unsigned long long aal = bcast2(a_s[ty * 4 + i]);
#pragma unroll
            for (int j = 0; j < 8; j++) mul2(o2[i][j], aal);
        }

        // ---- O += P V  in two 64-row V halves ----
#pragma unroll
        for (int h = 0; h < 2; h++) {
#pragma unroll
            for (int t = 0; t < 16; t++) {
                int e = tid + t * 256;
                int mm = e >> 6, cq = (e & 63) << 2;
                *(float4*)&Vs[mm * 256 + cq] =
                    *(const float4*)&vg[(size_t)(m0 + h * 64 + mm) * CC + cq];
            }
            __syncthreads();

#pragma unroll 2
            for (int mm = 0; mm < 64; mm++) {
                unsigned long long aa0 = bcast2(Ps[(ty * 4 + 0) * 132 + h * 64 + mm]);
                unsigned long long aa1 = bcast2(Ps[(ty * 4 + 1) * 132 + h * 64 + mm]);
                unsigned long long aa2 = bcast2(Ps[(ty * 4 + 2) * 132 + h * 64 + mm]);
                unsigned long long aa3 = bcast2(Ps[(ty * 4 + 3) * 132 + h * 64 + mm]);
#pragma unroll
                for (int q = 0; q < 4; q++) {
                    ulonglong2 v2 = *(const ulonglong2*)&Vs[mm * 256 + q * 64 + tx * 4];
                    fma2(o2[0][2 * q], aa0, v2.x); fma2(o2[0][2 * q + 1], aa0, v2.y);
                    fma2(o2[1][2 * q], aa1, v2.x); fma2(o2[1][2 * q + 1], aa1, v2.y);
                    fma2(o2[2][2 * q], aa2, v2.x); fma2(o2[2][2 * q + 1], aa2, v2.y);
                    fma2(o2[3][2 * q], aa3, v2.x); fma2(o2[3][2 * q + 1], aa3, v2.y);
                }
            }
            __syncthreads();
        }
    }

    // ---- epilogue: out[b][c][n] = gamma * O[n][c]/l[n] + x_main[b][c][n] ----
    const float gma = gamma_p[0];
    float inv_l[4];
#pragma unroll
    for (int i = 0; i < 4; i++) inv_l[i] = 1.0f / l_s[ty * 4 + i];

    float* Ts = smf;  // reuse Qs region: [64 c][65]
    const float* xb = x_main + (size_t)b * CC * NN;
    float* ob = out + (size_t)b * CC * NN;

#pragma unroll
    for (int q = 0; q < 4; q++) {
        __syncthreads();
#pragma unroll
        for (int i = 0; i < 4; i++) {
            float2 f0 = up2(o2[i][2 * q]);       // u = 0,1
            float2 f1 = up2(o2[i][2 * q + 1]);   // u = 2,3
            Ts[(tx * 4 + 0) * 65 + ty * 4 + i] = f0.x * inv_l[i];
            Ts[(tx * 4 + 1) * 65 + ty * 4 + i] = f0.y * inv_l[i];
            Ts[(tx * 4 + 2) * 65 + ty * 4 + i] = f1.x * inv_l[i];
            Ts[(tx * 4 + 3) * 65 + ty * 4 + i] = f1.y * inv_l[i];
        }
        __syncthreads();
#pragma unroll
        for (int t = 0; t < 16; t++) {
            int e = tid + t * 256;
            int cl = e >> 6, nl = e & 63;
            size_t gi = (size_t)(q * 64 + cl) * NN + n0 + nl;
            ob[gi] = gma * Ts[cl * 65 + nl] + xb[gi];
        }
    }
}

// ---------------------------------------------------------------------------
extern "C" void kernel_launch(void* const* d_in, const int* in_sizes, int n_in,
                              void* d_out, int out_size) {
    const float* x  = (const float*)d_in[0];
    const float* z  = (const float*)d_in[1];
    const float* Wq = (const float*)d_in[2];
    const float* bq = (const float*)d_in[3];
    const float* Wk = (const float*)d_in[4];
    const float* bk = (const float*)d_in[5];
    const float* Wv = (const float*)d_in[6];
    const float* bv = (const float*)d_in[7];
    const float* ga = (const float*)d_in[8];
    float* out = (float*)d_out;

    cudaFuncSetAttribute(attn_kernel, cudaFuncAttributeMaxDynamicSharedMemorySize,
                         ATTN_SMEM_BYTES);

    dim3 blk(256);
    proj_all_kernel<<<dim3(64, 4, BB), blk>>>(x, z, Wq, bq, Wk, bk, Wv, bv);
    attn_kernel<<<dim3(NN / 64, BB), blk, ATTN_SMEM_BYTES>>>(x, ga, out);
}

// round 7
// speedup vs baseline: 1.8745x; 1.8745x over previous
#include <cuda_runtime.h>
#include <cuda_bf16.h>
#include <cstdint>

#define BB 4
#define CC 256
#define CI 128
#define NN 4096
#define MT 128            // q-rows per CTA
#define MS 128            // m chunk
#define NCH (NN / MS)

// Scratch (static __device__)
__device__ __align__(16) __nv_bfloat16 g_qh[BB * NN * CI];   // [b][n][ci]
__device__ __align__(16) __nv_bfloat16 g_ql[BB * NN * CI];
__device__ __align__(16) __nv_bfloat16 g_kh[BB * NN * CI];   // [b][m][ci]
__device__ __align__(16) __nv_bfloat16 g_kl[BB * NN * CI];
__device__ __align__(16) __nv_bfloat16 g_vt[BB * CC * NN];   // [b][c][m]

// smem byte offsets; row pitch 272B (256B data + 16B pad -> conflict-free ldmatrix)
#define RP    272
#define SQH   0
#define SQL   (SQH + 128 * RP)
#define SKH   (SQL + 128 * RP)
#define SKL   (SKH + 128 * RP)
#define SVT   (SKL + 128 * RP)
#define SMEM_TOTAL (SVT + 256 * RP)    // 208896 B

// ---------------------------------------------------------------------------
// PTX helpers (all plain sm_80+ PTX — compiles for sm_103)
// ---------------------------------------------------------------------------
__device__ __forceinline__ uint32_t s2u(const void* p) {
    uint32_t a;
    asm("{ .reg .u64 t; cvta.to.shared.u64 t, %1; cvt.u32.u64 %0, t; }"
        : "=r"(a) : "l"(p));
    return a;
}
__device__ __forceinline__ void ldsm4(uint32_t* r, uint32_t addr) {
    asm volatile("ldmatrix.sync.aligned.m8n8.x4.shared.b16 {%0,%1,%2,%3}, [%4];\n"
                 : "=r"(r[0]), "=r"(r[1]), "=r"(r[2]), "=r"(r[3]) : "r"(addr));
}
__device__ __forceinline__ void mma_bf16(float* c, const uint32_t* a,
                                         const uint32_t* b) {
    asm volatile(
        "mma.sync.aligned.m16n8k16.row.col.f32.bf16.bf16.f32 "
        "{%0,%1,%2,%3}, {%4,%5,%6,%7}, {%8,%9}, {%0,%1,%2,%3};\n"
        : "+f"(c[0]), "+f"(c[1]), "+f"(c[2]), "+f"(c[3])
        : "r"(a[0]), "r"(a[1]), "r"(a[2]), "r"(a[3]), "r"(b[0]), "r"(b[1]));
}
__device__ __forceinline__ uint32_t pk2(float hi, float lo) {
    uint32_t r;
    asm("cvt.rn.bf16x2.f32 %0, %1, %2;" : "=r"(r) : "f"(hi), "f"(lo));
    return r;
}
__device__ __forceinline__ void cpa16(uint32_t dst, const void* src) {
    asm volatile("cp.async.cg.shared.global [%0], [%1], 16;\n"
                 :: "r"(dst), "l"(src));
}
#define CP_COMMIT() asm volatile("cp.async.commit_group;\n" ::: "memory")
#define CP_WAIT1()  asm volatile("cp.async.wait_group 1;\n" ::: "memory")
#define CP_WAIT0()  asm volatile("cp.async.wait_group 0;\n" ::: "memory")

// ---------------------------------------------------------------------------
// Projections: fp32 SIMT, bf16(+residual) outputs. (round-4 proven core)
// ---------------------------------------------------------------------------
template <bool TRANS>
__device__ __forceinline__ void proj_body(const float* __restrict__ in,
                                          const float* __restrict__ W,
                                          const float* __restrict__ bias,
                                          __nv_bfloat16* __restrict__ out_hi,
                                          __nv_bfloat16* __restrict__ out_lo,
                                          int Cin, int O, int o0) {
    __shared__ float Xs[32 * 64];
    __shared__ float Ws[32 * 132];

    const int tid = threadIdx.x;
    const int ty = tid >> 4;
    const int tx = tid & 15;
    const int n0 = blockIdx.x * 64;
    const int b  = blockIdx.z;
    const float* inb = in + (size_t)b * Cin * NN;

    float acc[4][8];
#pragma unroll
    for (int i = 0; i < 4; i++)
#pragma unroll
        for (int j = 0; j < 8; j++) acc[i][j] = 0.f;

    for (int c0 = 0; c0 < Cin; c0 += 32) {
#pragma unroll
        for (int t = 0; t < 8; t++) {
            int e = tid + t * 256;
            int cc = e >> 6, nn = e & 63;
            Xs[cc * 64 + nn] = inb[(size_t)(c0 + cc) * NN + n0 + nn];
        }
#pragma unroll
        for (int t = 0; t < 16; t++) {
            int e = tid + t * 256;
            int oo = e >> 5, cc = e & 31;
            Ws[cc * 132 + oo] = W[(size_t)(o0 + oo) * Cin + c0 + cc];
        }
        __syncthreads();

#pragma unroll 4
        for (int cc = 0; cc < 32; cc++) {
            float4 w0 = *(const float4*)&Ws[cc * 132 + tx * 4];
            float4 w1 = *(const float4*)&Ws[cc * 132 + 64 + tx * 4];
#pragma unroll
            for (int i = 0; i < 4; i++) {
                float a = Xs[cc * 64 + ty * 4 + i];
                acc[i][0] += a * w0.x; acc[i][1] += a * w0.y;
                acc[i][2] += a * w0.z; acc[i][3] += a * w0.w;
                acc[i][4] += a * w1.x; acc[i][5] += a * w1.y;
                acc[i][6] += a * w1.z; acc[i][7] += a * w1.w;
            }
        }
        __syncthreads();
    }

    float bj[8];
#pragma unroll
    for (int u = 0; u < 4; u++) {
        bj[u]     = bias[o0 + tx * 4 + u];
        bj[4 + u] = bias[o0 + 64 + tx * 4 + u];
    }

    if (!TRANS) {
#pragma unroll
        for (int i = 0; i < 4; i++) {
            size_t base = ((size_t)b * NN + n0 + ty * 4 + i) * (size_t)O + o0;
#pragma unroll
            for (int hf = 0; hf < 2; hf++) {
                size_t idx = base + hf * 64 + tx * 4;
#pragma unroll
                for (int p = 0; p < 2; p++) {
                    float v0 = acc[i][hf * 4 + 2 * p]     + bj[hf * 4 + 2 * p];
                    float v1 = acc[i][hf * 4 + 2 * p + 1] + bj[hf * 4 + 2 * p + 1];
                    __nv_bfloat16 h0 = __float2bfloat16(v0);
                    __nv_bfloat16 h1 = __float2bfloat16(v1);
                    *(__nv_bfloat162*)&out_hi[idx + 2 * p] = __halves2bfloat162(h0, h1);
                    __nv_bfloat16 l0 = __float2bfloat16(v0 - __bfloat162float(h0));
                    __nv_bfloat16 l1 = __float2bfloat16(v1 - __bfloat162float(h1));
                    *(__nv_bfloat162*)&out_lo[idx + 2 * p] = __halves2bfloat162(l0, l1);
                }
            }
        }
    } else {
#pragma unroll
        for (int hf = 0; hf < 2; hf++)
#pragma unroll
            for (int u = 0; u < 4; u++) {
                int o = o0 + hf * 64 + tx * 4 + u;
                float bb2 = bj[hf * 4 + u];
                size_t base = ((size_t)b * CC + o) * NN + n0 + ty * 4;
                __nv_bfloat16 h0 = __float2bfloat16(acc[0][hf * 4 + u] + bb2);
                __nv_bfloat16 h1 = __float2bfloat16(acc[1][hf * 4 + u] + bb2);
                __nv_bfloat16 h2 = __float2bfloat16(acc[2][hf * 4 + u] + bb2);
                __nv_bfloat16 h3 = __float2bfloat16(acc[3][hf * 4 + u] + bb2);
                *(__nv_bfloat162*)&out_hi[base]     = __halves2bfloat162(h0, h1);
                *(__nv_bfloat162*)&out_hi[base + 2] = __halves2bfloat162(h2, h3);
            }
    }
}

__global__ __launch_bounds__(256) void proj_all_kernel(
    const float* __restrict__ x, const float* __restrict__ z,
    const float* __restrict__ Wq, const float* __restrict__ bq,
    const float* __restrict__ Wk, const float* __restrict__ bk,
    const float* __restrict__ Wv, const float* __restrict__ bv) {
    int sel = blockIdx.y;
    if (sel == 0)
        proj_body<false>(x, Wq, bq, g_qh, g_ql, 256, 128, 0);
    else if (sel == 1)
        proj_body<false>(z, Wk, bk, g_kh, g_kl, 256, 128, 0);
    else
        proj_body<true>(z, Wv, bv, g_vt, nullptr, 256, 256, (sel - 2) * 128);
}

// ---------------------------------------------------------------------------
// cp.async chunk loaders
// ---------------------------------------------------------------------------
__device__ __forceinline__ void load_k_chunk(uint32_t sb, int b, int m0, int tid) {
    const char* kh = (const char*)(g_kh + ((size_t)b * NN + m0) * CI);
    const char* kl = (const char*)(g_kl + ((size_t)b * NN + m0) * CI);
#pragma unroll
    for (int t = 0; t < 8; t++) {
        int e = tid + t * 256;
        int r = e >> 4, c16 = (e & 15) * 16;
        cpa16(sb + SKH + r * RP + c16, kh + r * 256 + c16);
        cpa16(sb + SKL + r * RP + c16, kl + r * 256 + c16);
    }
}
__device__ __forceinline__ void load_v_chunk(uint32_t sb, int b, int m0, int tid) {
    const char* vt = (const char*)(g_vt + (size_t)b * CC * NN + m0);
#pragma unroll
    for (int t = 0; t < 16; t++) {
        int e = tid + t * 256;
        int r = e >> 4, c16 = (e & 15) * 16;
        cpa16(sb + SVT + r * RP + c16, vt + (size_t)r * (NN * 2) + c16);
    }
}

// ---------------------------------------------------------------------------
// Flash attention via mma.sync m16n8k16 bf16. 8 warps; warp = 16 q-rows.
// ---------------------------------------------------------------------------
__global__ __launch_bounds__(256, 1)
void attn_kernel(const float* __restrict__ x_main,
                 const float* __restrict__ gamma_p,
                 float* __restrict__ out) {
    extern __shared__ char sm[];
    const uint32_t sb = s2u(sm);
    const int tid = threadIdx.x;
    const int w = tid >> 5, lane = tid & 31;
    const int g = lane >> 2, tp = lane & 3;
    const int n0 = blockIdx.x * MT;
    const int b  = blockIdx.y;
    const int q0 = w * 16;

    // ldmatrix lane addressing (precomputed offsets within a tile-group)
    const uint32_t a_row = q0 + (lane & 15);
    const uint32_t a_koff = (lane >> 4) * 16;          // bytes (8 bf16)
    const uint32_t b_row7 = lane & 7;
    const uint32_t b_koff = (lane >> 3) * 16;          // bytes

    // Load Q (plain, one-time)
    {
        const char* qh = (const char*)(g_qh + ((size_t)b * NN + n0) * CI);
        const char* ql = (const char*)(g_ql + ((size_t)b * NN + n0) * CI);
#pragma unroll
        for (int t = 0; t < 8; t++) {
            int e = tid + t * 256;
            int r = e >> 4, c16 = (e & 15) * 16;
            *(uint4*)(sm + SQH + r * RP + c16) = *(const uint4*)(qh + r * 256 + c16);
            *(uint4*)(sm + SQL + r * RP + c16) = *(const uint4*)(ql + r * 256 + c16);
        }
    }
    load_k_chunk(sb, b, 0, tid); CP_COMMIT();
    load_v_chunk(sb, b, 0, tid); CP_COMMIT();
    __syncthreads();

    float o[32][4];
#pragma unroll
    for (int j = 0; j < 32; j++)
#pragma unroll
        for (int i = 0; i < 4; i++) o[j][i] = 0.f;
    float l0 = 0.f, l1 = 0.f;
    uint32_t P[8][4];

    for (int ch = 0; ch < NCH; ch++) {
        CP_WAIT1();            // K[ch] resident (V[ch] may still fly)
        __syncthreads();

        // ================= S = Qh*Kh + Qh*Kl + Ql*Kh =================
#pragma unroll
        for (int h = 0; h < 2; h++) {
            float s[8][4];
#pragma unroll
            for (int j = 0; j < 8; j++)
#pragma unroll
                for (int i = 0; i < 4; i++) s[j][i] = 0.f;

#pragma unroll
            for (int term = 0; term < 3; term++) {
                const uint32_t Ab = sb + (term == 2 ? SQL : SQH);
                const uint32_t Bb = sb + (term == 1 ? SKL : SKH);
#pragma unroll
                for (int kk = 0; kk < 4; kk++) {
                    uint32_t a[8];
                    uint32_t ar = Ab + a_row * RP + kk * 64 + a_koff;
                    ldsm4(a, ar);
                    ldsm4(a + 4, ar + 32);
#pragma unroll
                    for (int j = 0; j < 8; j++) {
                        uint32_t bf[4];
                        ldsm4(bf, Bb + (h * 64 + j * 8 + b_row7) * RP +
                                   kk * 64 + b_koff);
                        mma_bf16(s[j], a, bf);
                        mma_bf16(s[j], a + 4, bf + 2);
                    }
                }
            }
            // exp (no max-subtraction) + pack to A-fragments + l accumulation
#pragma unroll
            for (int j2 = 0; j2 < 4; j2++) {
                int u = h * 4 + j2;
                float ea0 = __expf(s[2 * j2][0]);
                float ea1 = __expf(s[2 * j2][1]);
                float ea2 = __expf(s[2 * j2][2]);
                float ea3 = __expf(s[2 * j2][3]);
                float eb0 = __expf(s[2 * j2 + 1][0]);
                float eb1 = __expf(s[2 * j2 + 1][1]);
                float eb2 = __expf(s[2 * j2 + 1][2]);
                float eb3 = __expf(s[2 * j2 + 1][3]);
                l0 += (ea0 + ea1) + (eb0 + eb1);
                l1 += (ea2 + ea3) + (eb2 + eb3);
                P[u][0] = pk2(ea1, ea0);
                P[u][1] = pk2(ea3, ea2);
                P[u][2] = pk2(eb1, eb0);
                P[u][3] = pk2(eb3, eb2);
            }
        }
        __syncthreads();                  // everyone done reading K
        if (ch + 1 < NCH) load_k_chunk(sb, b, (ch + 1) * MS, tid);
        CP_COMMIT();

        CP_WAIT1();                       // V[ch] resident (K[ch+1] flying)
        __syncthreads();

        // ================= O += P @ V^T =================
#pragma unroll
        for (int j = 0; j < 32; j++) {
#pragma unroll
            for (int uu = 0; uu < 4; uu++) {
                uint32_t bf[4];
                ldsm4(bf, sb + SVT + (j * 8 + b_row7) * RP + uu * 64 + b_koff);
                mma_bf16(o[j], P[2 * uu], bf);
                mma_bf16(o[j], P[2 * uu + 1], bf + 2);
            }
        }
        __syncthreads();                  // everyone done reading V
        if (ch + 1 < NCH) load_v_chunk(sb, b, (ch + 1) * MS, tid);
        CP_COMMIT();
    }
    CP_WAIT0();

    // l across the 4-thread groups (rows g and g+8 of this warp)
    l0 += __shfl_xor_sync(0xffffffffu, l0, 1);
    l0 += __shfl_xor_sync(0xffffffffu, l0, 2);
    l1 += __shfl_xor_sync(0xffffffffu, l1, 1);
    l1 += __shfl_xor_sync(0xffffffffu, l1, 2);
    const float inv0 = 1.0f / l0, inv1 = 1.0f / l1;
    const float gma = gamma_p[0];

    __syncthreads();
    // stage O via smem (per-warp [256c][17] f32 region) for coalesced output
    float* st = (float*)(sm + w * 17408);
#pragma unroll
    for (int j = 0; j < 32; j++) {
        int c0 = j * 8 + 2 * tp;
        st[(c0)     * 17 + g]     = o[j][0] * inv0;
        st[(c0 + 1) * 17 + g]     = o[j][1] * inv0;
        st[(c0)     * 17 + g + 8] = o[j][2] * inv1;
        st[(c0 + 1) * 17 + g + 8] = o[j][3] * inv1;
    }
    __syncwarp();
    {
        const int q = lane & 15;
        const int ch2 = lane >> 4;
#pragma unroll 4
        for (int cc2 = 0; cc2 < 128; cc2++) {
            int c = cc2 * 2 + ch2;
            float v = st[c * 17 + q];
            size_t gi = ((size_t)b * CC + c) * NN + n0 + q0 + q;
            out[gi] = gma * v + x_main[gi];
        }
    }
}

// ---------------------------------------------------------------------------
extern "C" void kernel_launch(void* const* d_in, const int* in_sizes, int n_in,
                              void* d_out, int out_size) {
    const float* x  = (const float*)d_in[0];
    const float* z  = (const float*)d_in[1];
    const float* Wq = (const float*)d_in[2];
    const float* bq = (const float*)d_in[3];
    const float* Wk = (const float*)d_in[4];
    const float* bk = (const float*)d_in[5];
    const float* Wv = (const float*)d_in[6];
    const float* bv = (const float*)d_in[7];
    const float* ga = (const float*)d_in[8];
    float* out = (float*)d_out;

    cudaFuncSetAttribute(attn_kernel, cudaFuncAttributeMaxDynamicSharedMemorySize,
                         SMEM_TOTAL);

    dim3 blk(256);
    proj_all_kernel<<<dim3(64, 4, BB), blk>>>(x, z, Wq, bq, Wk, bk, Wv, bv);
    attn_kernel<<<dim3(NN / MT, BB), blk, SMEM_TOTAL>>>(x, ga, out);
}

// round 10
// speedup vs baseline: 2.8599x; 1.5257x over previous
#include <cuda_runtime.h>
#include <cuda_bf16.h>
#include <cstdint>

#define BB 4
#define CC 256
#define CI 128
#define NN 4096
#define MT 128            // q-rows per CTA
#define MS 128            // m chunk
#define NCH (NN / MS)

// Scratch (static __device__)
__device__ __align__(16) __nv_bfloat16 g_qh[BB * NN * CI];   // [b][n][ci]
__device__ __align__(16) __nv_bfloat16 g_ql[BB * NN * CI];
__device__ __align__(16) __nv_bfloat16 g_kh[BB * NN * CI];   // [b][m][ci]
__device__ __align__(16) __nv_bfloat16 g_kl[BB * NN * CI];
__device__ __align__(16) __nv_bfloat16 g_vt[BB * CC * NN];   // [b][c][m]

// smem byte offsets; row pitch 272B (256B data + 16B pad -> conflict-free ldmatrix)
#define RP    272
#define SQH   0
#define SQL   (SQH + 128 * RP)
#define SKH   (SQL + 128 * RP)
#define SKL   (SKH + 128 * RP)
#define SVT   (SKL + 128 * RP)
#define SLSH  (SVT + 256 * RP)            // l exchange: 128 floats
#define SMEM_TOTAL (SLSH + 512)           // 209408 B

// ---------------------------------------------------------------------------
// PTX helpers (plain sm_80+ PTX — compiles for sm_103)
// ---------------------------------------------------------------------------
__device__ __forceinline__ uint32_t s2u(const void* p) {
    uint32_t a;
    asm("{ .reg .u64 t; cvta.to.shared.u64 t, %1; cvt.u32.u64 %0, t; }"
        : "=r"(a) : "l"(p));
    return a;
}
__device__ __forceinline__ void ldsm4(uint32_t* r, uint32_t addr) {
    asm volatile("ldmatrix.sync.aligned.m8n8.x4.shared.b16 {%0,%1,%2,%3}, [%4];\n"
                 : "=r"(r[0]), "=r"(r[1]), "=r"(r[2]), "=r"(r[3]) : "r"(addr));
}
__device__ __forceinline__ void mma_bf16(float* c, const uint32_t* a,
                                         const uint32_t* b) {
    asm volatile(
        "mma.sync.aligned.m16n8k16.row.col.f32.bf16.bf16.f32 "
        "{%0,%1,%2,%3}, {%4,%5,%6,%7}, {%8,%9}, {%0,%1,%2,%3};\n"
        : "+f"(c[0]), "+f"(c[1]), "+f"(c[2]), "+f"(c[3])
        : "r"(a[0]), "r"(a[1]), "r"(a[2]), "r"(a[3]), "r"(b[0]), "r"(b[1]));
}
__device__ __forceinline__ uint32_t pk2(float hi, float lo) {
    uint32_t r;
    asm("cvt.rn.bf16x2.f32 %0, %1, %2;" : "=r"(r) : "f"(hi), "f"(lo));
    return r;
}
__device__ __forceinline__ void cpa16(uint32_t dst, const void* src) {
    asm volatile("cp.async.cg.shared.global [%0], [%1], 16;\n"
                 :: "r"(dst), "l"(src));
}
#define CP_COMMIT() asm volatile("cp.async.commit_group;\n" ::: "memory")
#define CP_WAIT1()  asm volatile("cp.async.wait_group 1;\n" ::: "memory")
#define CP_WAIT0()  asm volatile("cp.async.wait_group 0;\n" ::: "memory")

// ---------------------------------------------------------------------------
// Projections: fp32 SIMT, bf16(+residual) outputs (round-4 proven core)
// ---------------------------------------------------------------------------
template <bool TRANS>
__device__ __forceinline__ void proj_body(const float* __restrict__ in,
                                          const float* __restrict__ W,
                                          const float* __restrict__ bias,
                                          __nv_bfloat16* __restrict__ out_hi,
                                          __nv_bfloat16* __restrict__ out_lo,
                                          int Cin, int O, int o0) {
    __shared__ float Xs[32 * 64];
    __shared__ float Ws[32 * 132];

    const int tid = threadIdx.x;
    const int ty = tid >> 4;
    const int tx = tid & 15;
    const int n0 = blockIdx.x * 64;
    const int b  = blockIdx.z;
    const float* inb = in + (size_t)b * Cin * NN;

    float acc[4][8];
#pragma unroll
    for (int i = 0; i < 4; i++)
#pragma unroll
        for (int j = 0; j < 8; j++) acc[i][j] = 0.f;

    for (int c0 = 0; c0 < Cin; c0 += 32) {
#pragma unroll
        for (int t = 0; t < 8; t++) {
            int e = tid + t * 256;
            int cc = e >> 6, nn = e & 63;
            Xs[cc * 64 + nn] = inb[(size_t)(c0 + cc) * NN + n0 + nn];
        }
#pragma unroll
        for (int t = 0; t < 16; t++) {
            int e = tid + t * 256;
            int oo = e >> 5, cc = e & 31;
            Ws[cc * 132 + oo] = W[(size_t)(o0 + oo) * Cin + c0 + cc];
        }
        __syncthreads();

#pragma unroll 4
        for (int cc = 0; cc < 32; cc++) {
            float4 w0 = *(const float4*)&Ws[cc * 132 + tx * 4];
            float4 w1 = *(const float4*)&Ws[cc * 132 + 64 + tx * 4];
#pragma unroll
            for (int i = 0; i < 4; i++) {
                float a = Xs[cc * 64 + ty * 4 + i];
                acc[i][0] += a * w0.x; acc[i][1] += a * w0.y;
                acc[i][2] += a * w0.z; acc[i][3] += a * w0.w;
                acc[i][4] += a * w1.x; acc[i][5] += a * w1.y;
                acc[i][6] += a * w1.z; acc[i][7] += a * w1.w;
            }
        }
        __syncthreads();
    }

    float bj[8];
#pragma unroll
    for (int u = 0; u < 4; u++) {
        bj[u]     = bias[o0 + tx * 4 + u];
        bj[4 + u] = bias[o0 + 64 + tx * 4 + u];
    }

    if (!TRANS) {
#pragma unroll
        for (int i = 0; i < 4; i++) {
            size_t base = ((size_t)b * NN + n0 + ty * 4 + i) * (size_t)O + o0;
#pragma unroll
            for (int hf = 0; hf < 2; hf++) {
                size_t idx = base + hf * 64 + tx * 4;
#pragma unroll
                for (int p = 0; p < 2; p++) {
                    float v0 = acc[i][hf * 4 + 2 * p]     + bj[hf * 4 + 2 * p];
                    float v1 = acc[i][hf * 4 + 2 * p + 1] + bj[hf * 4 + 2 * p + 1];
                    __nv_bfloat16 h0 = __float2bfloat16(v0);
                    __nv_bfloat16 h1 = __float2bfloat16(v1);
                    *(__nv_bfloat162*)&out_hi[idx + 2 * p] = __halves2bfloat162(h0, h1);
                    __nv_bfloat16 l0 = __float2bfloat16(v0 - __bfloat162float(h0));
                    __nv_bfloat16 l1 = __float2bfloat16(v1 - __bfloat162float(h1));
                    *(__nv_bfloat162*)&out_lo[idx + 2 * p] = __halves2bfloat162(l0, l1);
                }
            }
        }
    } else {
#pragma unroll
        for (int hf = 0; hf < 2; hf++)
#pragma unroll
            for (int u = 0; u < 4; u++) {
                int o = o0 + hf * 64 + tx * 4 + u;
                float bb2 = bj[hf * 4 + u];
                size_t base = ((size_t)b * CC + o) * NN + n0 + ty * 4;
                __nv_bfloat16 h0 = __float2bfloat16(acc[0][hf * 4 + u] + bb2);
                __nv_bfloat16 h1 = __float2bfloat16(acc[1][hf * 4 + u] + bb2);
                __nv_bfloat16 h2 = __float2bfloat16(acc[2][hf * 4 + u] + bb2);
                __nv_bfloat16 h3 = __float2bfloat16(acc[3][hf * 4 + u] + bb2);
                *(__nv_bfloat162*)&out_hi[base]     = __halves2bfloat162(h0, h1);
                *(__nv_bfloat162*)&out_hi[base + 2] = __halves2bfloat162(h2, h3);
            }
    }
}

__global__ __launch_bounds__(256) void proj_all_kernel(
    const float* __restrict__ x, const float* __restrict__ z,
    const float* __restrict__ Wq, const float* __restrict__ bq,
    const float* __restrict__ Wk, const float* __restrict__ bk,
    const float* __restrict__ Wv, const float* __restrict__ bv) {
    int sel = blockIdx.y;
    if (sel == 0)
        proj_body<false>(x, Wq, bq, g_qh, g_ql, 256, 128, 0);
    else if (sel == 1)
        proj_body<false>(z, Wk, bk, g_kh, g_kl, 256, 128, 0);
    else
        proj_body<true>(z, Wv, bv, g_vt, nullptr, 256, 256, (sel - 2) * 128);
}

// ---------------------------------------------------------------------------
// cp.async chunk loaders (512 threads)
// ---------------------------------------------------------------------------
__device__ __forceinline__ void load_k_chunk(uint32_t sb, int b, int m0, int tid) {
    const char* kh = (const char*)(g_kh + ((size_t)b * NN + m0) * CI);
    const char* kl = (const char*)(g_kl + ((size_t)b * NN + m0) * CI);
#pragma unroll
    for (int t = 0; t < 4; t++) {
        int e = tid + t * 512;
        int r = e >> 4, c16 = (e & 15) * 16;
        cpa16(sb + SKH + r * RP + c16, kh + r * 256 + c16);
        cpa16(sb + SKL + r * RP + c16, kl + r * 256 + c16);
    }
}
__device__ __forceinline__ void load_v_chunk(uint32_t sb, int b, int m0, int tid) {
    const char* vt = (const char*)(g_vt + (size_t)b * CC * NN + m0);
#pragma unroll
    for (int t = 0; t < 8; t++) {
        int e = tid + t * 512;
        int r = e >> 4, c16 = (e & 15) * 16;
        cpa16(sb + SVT + r * RP + c16, vt + (size_t)r * (NN * 2) + c16);
    }
}

// ---------------------------------------------------------------------------
// Flash attention, mma.sync bf16. 16 warps: pair = q-rows, h = m-half.
// Each warp keeps private partial O/l over its m-half; combined once at end.
// ---------------------------------------------------------------------------
__global__ __launch_bounds__(512, 1)
void attn_kernel(const float* __restrict__ x_main,
                 const float* __restrict__ gamma_p,
                 float* __restrict__ out) {
    extern __shared__ char sm[];
    const uint32_t sb = s2u(sm);
    const int tid = threadIdx.x;
    const int w = tid >> 5, lane = tid & 31;
    const int pair = w >> 1, h = w & 1;
    const int g = lane >> 2, tp = lane & 3;
    const int n0 = blockIdx.x * MT;
    const int b  = blockIdx.y;
    const int q0 = pair * 16;

    const uint32_t a_row = q0 + (lane & 15);
    const uint32_t a_koff = (lane >> 4) * 16;
    const uint32_t b_row7 = lane & 7;
    const uint32_t b_koff = (lane >> 3) * 16;

    // Load Q (one-time)
    {
        const char* qh = (const char*)(g_qh + ((size_t)b * NN + n0) * CI);
        const char* ql = (const char*)(g_ql + ((size_t)b * NN + n0) * CI);
#pragma unroll
        for (int t = 0; t < 4; t++) {
            int e = tid + t * 512;
            int r = e >> 4, c16 = (e & 15) * 16;
            *(uint4*)(sm + SQH + r * RP + c16) = *(const uint4*)(qh + r * 256 + c16);
            *(uint4*)(sm + SQL + r * RP + c16) = *(const uint4*)(ql + r * 256 + c16);
        }
    }
    load_k_chunk(sb, b, 0, tid); CP_COMMIT();
    load_v_chunk(sb, b, 0, tid); CP_COMMIT();
    __syncthreads();

    float o[32][4];
#pragma unroll
    for (int j = 0; j < 32; j++)
#pragma unroll
        for (int i = 0; i < 4; i++) o[j][i] = 0.f;
    float l0 = 0.f, l1 = 0.f;
    uint32_t P[4][4];

    for (int ch = 0; ch < NCH; ch++) {
        CP_WAIT1();            // K[ch] resident (V[ch] may still fly)
        __syncthreads();

        // ===== S = Qh*Kh + Qh*Kl + Ql*Kh  (this warp: m in [64h, 64h+64)) =====
        float s[8][4];
#pragma unroll
        for (int j = 0; j < 8; j++)
#pragma unroll
            for (int i = 0; i < 4; i++) s[j][i] = 0.f;

#pragma unroll
        for (int kk = 0; kk < 4; kk++) {
            uint32_t ah[8], al[8];
            uint32_t ar = sb + SQH + a_row * RP + kk * 64 + a_koff;
            ldsm4(ah, ar); ldsm4(ah + 4, ar + 32);
            uint32_t ar2 = sb + SQL + a_row * RP + kk * 64 + a_koff;
            ldsm4(al, ar2); ldsm4(al + 4, ar2 + 32);
#pragma unroll
            for (int j = 0; j < 8; j++) {
                uint32_t br = (h * 64 + j * 8 + b_row7) * RP + kk * 64 + b_koff;
                uint32_t bh[4], bl[4];
                ldsm4(bh, sb + SKH + br);
                ldsm4(bl, sb + SKL + br);
                mma_bf16(s[j], ah, bh); mma_bf16(s[j], ah + 4, bh + 2);
                mma_bf16(s[j], ah, bl); mma_bf16(s[j], ah + 4, bl + 2);
                mma_bf16(s[j], al, bh); mma_bf16(s[j], al + 4, bh + 2);
            }
        }
        // exp (no max-subtraction) + pack to A-fragments + l accumulation
#pragma unroll
        for (int u = 0; u < 4; u++) {
            float ea0 = __expf(s[2 * u][0]);
            float ea1 = __expf(s[2 * u][1]);
            float ea2 = __expf(s[2 * u][2]);
            float ea3 = __expf(s[2 * u][3]);
            float eb0 = __expf(s[2 * u + 1][0]);
            float eb1 = __expf(s[2 * u + 1][1]);
            float eb2 = __expf(s[2 * u + 1][2]);
            float eb3 = __expf(s[2 * u + 1][3]);
            l0 += (ea0 + ea1) + (eb0 + eb1);
            l1 += (ea2 + ea3) + (eb2 + eb3);
            P[u][0] = pk2(ea1, ea0);
            P[u][1] = pk2(ea3, ea2);
            P[u][2] = pk2(eb1, eb0);
            P[u][3] = pk2(eb3, eb2);
        }
        __syncthreads();                  // everyone done reading K
        if (ch + 1 < NCH) load_k_chunk(sb, b, (ch + 1) * MS, tid);
        CP_COMMIT();

        CP_WAIT1();                       // V[ch] resident (K[ch+1] flying)
        __syncthreads();

        // ===== O += P @ V^T (only this warp's m-half) =====
#pragma unroll
        for (int j = 0; j < 32; j++) {
#pragma unroll
            for (int uu = 0; uu < 2; uu++) {
                uint32_t bf[4];
                ldsm4(bf, sb + SVT + (j * 8 + b_row7) * RP + h * 128 +
                          uu * 64 + b_koff);
                mma_bf16(o[j], P[2 * uu], bf);
                mma_bf16(o[j], P[2 * uu + 1], bf + 2);
            }
        }
        __syncthreads();                  // everyone done reading V
        if (ch + 1 < NCH) load_v_chunk(sb, b, (ch + 1) * MS, tid);
        CP_COMMIT();
    }
    CP_WAIT0();

    // l across the 4-thread groups (rows g and g+8 of this warp's 16 q-rows)
    l0 += __shfl_xor_sync(0xffffffffu, l0, 1);
    l0 += __shfl_xor_sync(0xffffffffu, l0, 2);
    l1 += __shfl_xor_sync(0xffffffffu, l1, 1);
    l1 += __shfl_xor_sync(0xffffffffu, l1, 2);

    // ===== combine the two m-half partials of each pair =====
    float* st = (float*)(sm + pair * 17408);        // [256 c][17] f32
    float* l_sh = (float*)(sm + SLSH);
    if (h == 0) {
#pragma unroll
        for (int j = 0; j < 32; j++) {
            int c0 = j * 8 + 2 * tp;
            st[(c0)     * 17 + g]     = o[j][0];
            st[(c0 + 1) * 17 + g]     = o[j][1];
            st[(c0)     * 17 + g + 8] = o[j][2];
            st[(c0 + 1) * 17 + g + 8] = o[j][3];
        }
        if (tp == 0) {
            l_sh[pair * 16 + g]     = l0;
            l_sh[pair * 16 + 8 + g] = l1;
        }
    }
    __syncthreads();
    if (h == 1) {
        const float inv0 = 1.0f / (l_sh[pair * 16 + g] + l0);
        const float inv1 = 1.0f / (l_sh[pair * 16 + 8 + g] + l1);
#pragma unroll
        for (int j = 0; j < 32; j++) {
            int c0 = j * 8 + 2 * tp;
            st[(c0)     * 17 + g]     = (st[(c0)     * 17 + g]     + o[j][0]) * inv0;
            st[(c0 + 1) * 17 + g]     = (st[(c0 + 1) * 17 + g]     + o[j][1]) * inv0;
            st[(c0)     * 17 + g + 8] = (st[(c0)     * 17 + g + 8] + o[j][2]) * inv1;
            st[(c0 + 1) * 17 + g + 8] = (st[(c0 + 1) * 17 + g + 8] + o[j][3]) * inv1;
        }
        __syncwarp();
        const float gma = gamma_p[0];
        const int q = lane & 15;
        const int ch2 = lane >> 4;
#pragma unroll 4
        for (int cc2 = 0; cc2 < 128; cc2++) {
            int c = cc2 * 2 + ch2;
            float v = st[c * 17 + q];
            size_t gi = ((size_t)b * CC + c) * NN + n0 + q0 + q;
            out[gi] = gma * v + x_main[gi];
        }
    }
}

// ---------------------------------------------------------------------------
extern "C" void kernel_launch(void* const* d_in, const int* in_sizes, int n_in,
                              void* d_out, int out_size) {
    const float* x  = (const float*)d_in[0];
    const float* z  = (const float*)d_in[1];
    const float* Wq = (const float*)d_in[2];
    const float* bq = (const float*)d_in[3];
    const float* Wk = (const float*)d_in[4];
    const float* bk = (const float*)d_in[5];
    const float* Wv = (const float*)d_in[6];
    const float* bv = (const float*)d_in[7];
    const float* ga = (const float*)d_in[8];
    float* out = (float*)d_out;

    cudaFuncSetAttribute(attn_kernel, cudaFuncAttributeMaxDynamicSharedMemorySize,
                         SMEM_TOTAL);

    proj_all_kernel<<<dim3(64, 4, BB), dim3(256)>>>(x, z, Wq, bq, Wk, bk, Wv, bv);
    attn_kernel<<<dim3(NN / MT, BB), dim3(512), SMEM_TOTAL>>>(x, ga, out);
}

// round 11
// speedup vs baseline: 4.0719x; 1.4238x over previous
#include <cuda_runtime.h>
#include <cuda_bf16.h>
#include <cstdint>

#define BB 4
#define CC 256
#define CI 128
#define NN 4096
#define MT 128            // q-rows per CTA
#define MS 128            // m chunk
#define NCH (NN / MS)

// Scratch (static __device__)
__device__ __align__(16) __nv_bfloat16 g_qh[BB * NN * CI];   // [b][n][ci]
__device__ __align__(16) __nv_bfloat16 g_ql[BB * NN * CI];
__device__ __align__(16) __nv_bfloat16 g_kh[BB * NN * CI];   // [b][m][ci]
__device__ __align__(16) __nv_bfloat16 g_kl[BB * NN * CI];
__device__ __align__(16) __nv_bfloat16 g_vt[BB * CC * NN];   // [b][c][m]

// smem byte offsets; row pitch 272B (256B data + 16B pad -> conflict-free ldmatrix)
#define RP    272
#define SQH   0
#define SQL   (SQH + 128 * RP)
#define SKH   (SQL + 128 * RP)
#define SKL   (SKH + 128 * RP)
#define SVT   (SKL + 128 * RP)
#define SPST  (SVT + 256 * RP)            // P exchange stage: 8 pairs x 2KB = 16KB
#define SLSH  (SPST + 16384)              // l exchange: 256 floats
#define SMEM_TOTAL (SLSH + 1024)          // 226304 B  (cap 232448)

// ---------------------------------------------------------------------------
// PTX helpers (plain sm_80+ PTX — compiles for sm_103)
// ---------------------------------------------------------------------------
__device__ __forceinline__ uint32_t s2u(const void* p) {
    uint32_t a;
    asm("{ .reg .u64 t; cvta.to.shared.u64 t, %1; cvt.u32.u64 %0, t; }"
        : "=r"(a) : "l"(p));
    return a;
}
__device__ __forceinline__ void ldsm4(uint32_t* r, uint32_t addr) {
    asm volatile("ldmatrix.sync.aligned.m8n8.x4.shared.b16 {%0,%1,%2,%3}, [%4];\n"
                 : "=r"(r[0]), "=r"(r[1]), "=r"(r[2]), "=r"(r[3]) : "r"(addr));
}
__device__ __forceinline__ void mma_bf16(float* c, const uint32_t* a,
                                         const uint32_t* b) {
    asm volatile(
        "mma.sync.aligned.m16n8k16.row.col.f32.bf16.bf16.f32 "
        "{%0,%1,%2,%3}, {%4,%5,%6,%7}, {%8,%9}, {%0,%1,%2,%3};\n"
        : "+f"(c[0]), "+f"(c[1]), "+f"(c[2]), "+f"(c[3])
        : "r"(a[0]), "r"(a[1]), "r"(a[2]), "r"(a[3]), "r"(b[0]), "r"(b[1]));
}
__device__ __forceinline__ uint32_t pk2(float hi, float lo) {
    uint32_t r;
    asm("cvt.rn.bf16x2.f32 %0, %1, %2;" : "=r"(r) : "f"(hi), "f"(lo));
    return r;
}
__device__ __forceinline__ void cpa16(uint32_t dst, const void* src) {
    asm volatile("cp.async.cg.shared.global [%0], [%1], 16;\n"
                 :: "r"(dst), "l"(src));
}
__device__ __forceinline__ void sts128(uint32_t addr, const uint32_t* v) {
    asm volatile("st.shared.v4.b32 [%0], {%1,%2,%3,%4};\n"
                 :: "r"(addr), "r"(v[0]), "r"(v[1]), "r"(v[2]), "r"(v[3]) : "memory");
}
__device__ __forceinline__ void ldsv4(uint32_t* v, uint32_t addr) {
    asm volatile("ld.shared.v4.b32 {%0,%1,%2,%3}, [%4];\n"
                 : "=r"(v[0]), "=r"(v[1]), "=r"(v[2]), "=r"(v[3]) : "r"(addr));
}
__device__ __forceinline__ void barp(int id) {
    asm volatile("bar.sync %0, 64;\n" :: "r"(id) : "memory");
}
#define CP_COMMIT() asm volatile("cp.async.commit_group;\n" ::: "memory")
#define CP_WAIT1()  asm volatile("cp.async.wait_group 1;\n" ::: "memory")
#define CP_WAIT0()  asm volatile("cp.async.wait_group 0;\n" ::: "memory")

// ---------------------------------------------------------------------------
// Projections: fp32 SIMT, bf16(+residual) outputs (proven core)
// ---------------------------------------------------------------------------
template <bool TRANS>
__device__ __forceinline__ void proj_body(const float* __restrict__ in,
                                          const float* __restrict__ W,
                                          const float* __restrict__ bias,
                                          __nv_bfloat16* __restrict__ out_hi,
                                          __nv_bfloat16* __restrict__ out_lo,
                                          int Cin, int O, int o0) {
    __shared__ float Xs[32 * 64];
    __shared__ float Ws[32 * 132];

    const int tid = threadIdx.x;
    const int ty = tid >> 4;
    const int tx = tid & 15;
    const int n0 = blockIdx.x * 64;
    const int b  = blockIdx.z;
    const float* inb = in + (size_t)b * Cin * NN;

    float acc[4][8];
#pragma unroll
    for (int i = 0; i < 4; i++)
#pragma unroll
        for (int j = 0; j < 8; j++) acc[i][j] = 0.f;

    for (int c0 = 0; c0 < Cin; c0 += 32) {
#pragma unroll
        for (int t = 0; t < 8; t++) {
            int e = tid + t * 256;
            int cc = e >> 6, nn = e & 63;
            Xs[cc * 64 + nn] = inb[(size_t)(c0 + cc) * NN + n0 + nn];
        }
#pragma unroll
        for (int t = 0; t < 16; t++) {
            int e = tid + t * 256;
            int oo = e >> 5, cc = e & 31;
            Ws[cc * 132 + oo] = W[(size_t)(o0 + oo) * Cin + c0 + cc];
        }
        __syncthreads();

#pragma unroll 4
        for (int cc = 0; cc < 32; cc++) {
            float4 w0 = *(const float4*)&Ws[cc * 132 + tx * 4];
            float4 w1 = *(const float4*)&Ws[cc * 132 + 64 + tx * 4];
#pragma unroll
            for (int i = 0; i < 4; i++) {
                float a = Xs[cc * 64 + ty * 4 + i];
                acc[i][0] += a * w0.x; acc[i][1] += a * w0.y;
                acc[i][2] += a * w0.z; acc[i][3] += a * w0.w;
                acc[i][4] += a * w1.x; acc[i][5] += a * w1.y;
                acc[i][6] += a * w1.z; acc[i][7] += a * w1.w;
            }
        }
        __syncthreads();
    }

    float bj[8];
#pragma unroll
    for (int u = 0; u < 4; u++) {
        bj[u]     = bias[o0 + tx * 4 + u];
        bj[4 + u] = bias[o0 + 64 + tx * 4 + u];
    }

    if (!TRANS) {
#pragma unroll
        for (int i = 0; i < 4; i++) {
            size_t base = ((size_t)b * NN + n0 + ty * 4 + i) * (size_t)O + o0;
#pragma unroll
            for (int hf = 0; hf < 2; hf++) {
                size_t idx = base + hf * 64 + tx * 4;
#pragma unroll
                for (int p = 0; p < 2; p++) {
                    float v0 = acc[i][hf * 4 + 2 * p]     + bj[hf * 4 + 2 * p];
                    float v1 = acc[i][hf * 4 + 2 * p + 1] + bj[hf * 4 + 2 * p + 1];
                    __nv_bfloat16 h0 = __float2bfloat16(v0);
                    __nv_bfloat16 h1 = __float2bfloat16(v1);
                    *(__nv_bfloat162*)&out_hi[idx + 2 * p] = __halves2bfloat162(h0, h1);
                    __nv_bfloat16 l0 = __float2bfloat16(v0 - __bfloat162float(h0));
                    __nv_bfloat16 l1 = __float2bfloat16(v1 - __bfloat162float(h1));
                    *(__nv_bfloat162*)&out_lo[idx + 2 * p] = __halves2bfloat162(l0, l1);
                }
            }
        }
    } else {
#pragma unroll
        for (int hf = 0; hf < 2; hf++)
#pragma unroll
            for (int u = 0; u < 4; u++) {
                int o = o0 + hf * 64 + tx * 4 + u;
                float bb2 = bj[hf * 4 + u];
                size_t base = ((size_t)b * CC + o) * NN + n0 + ty * 4;
                __nv_bfloat16 h0 = __float2bfloat16(acc[0][hf * 4 + u] + bb2);
                __nv_bfloat16 h1 = __float2bfloat16(acc[1][hf * 4 + u] + bb2);
                __nv_bfloat16 h2 = __float2bfloat16(acc[2][hf * 4 + u] + bb2);
                __nv_bfloat16 h3 = __float2bfloat16(acc[3][hf * 4 + u] + bb2);
                *(__nv_bfloat162*)&out_hi[base]     = __halves2bfloat162(h0, h1);
                *(__nv_bfloat162*)&out_hi[base + 2] = __halves2bfloat162(h2, h3);
            }
    }
}

__global__ __launch_bounds__(256) void proj_all_kernel(
    const float* __restrict__ x, const float* __restrict__ z,
    const float* __restrict__ Wq, const float* __restrict__ bq,
    const float* __restrict__ Wk, const float* __restrict__ bk,
    const float* __restrict__ Wv, const float* __restrict__ bv) {
    int sel = blockIdx.y;
    if (sel == 0)
        proj_body<false>(x, Wq, bq, g_qh, g_ql, 256, 128, 0);
    else if (sel == 1)
        proj_body<false>(z, Wk, bk, g_kh, g_kl, 256, 128, 0);
    else
        proj_body<true>(z, Wv, bv, g_vt, nullptr, 256, 256, (sel - 2) * 128);
}

// ---------------------------------------------------------------------------
// cp.async chunk loaders (512 threads)
// ---------------------------------------------------------------------------
__device__ __forceinline__ void load_k_chunk(uint32_t sb, int b, int m0, int tid) {
    const char* kh = (const char*)(g_kh + ((size_t)b * NN + m0) * CI);
    const char* kl = (const char*)(g_kl + ((size_t)b * NN + m0) * CI);
#pragma unroll
    for (int t = 0; t < 4; t++) {
        int e = tid + t * 512;
        int r = e >> 4, c16 = (e & 15) * 16;
        cpa16(sb + SKH + r * RP + c16, kh + r * 256 + c16);
        cpa16(sb + SKL + r * RP + c16, kl + r * 256 + c16);
    }
}
__device__ __forceinline__ void load_v_chunk(uint32_t sb, int b, int m0, int tid) {
    const char* vt = (const char*)(g_vt + (size_t)b * CC * NN + m0);
#pragma unroll
    for (int t = 0; t < 8; t++) {
        int e = tid + t * 512;
        int r = e >> 4, c16 = (e & 15) * 16;
        cpa16(sb + SVT + r * RP + c16, vt + (size_t)r * (NN * 2) + c16);
    }
}

// ---------------------------------------------------------------------------
// Flash attention, mma.sync bf16. 16 warps = 8 pairs.
// S-phase: warp h of pair computes S for m-half h (no duplication).
// PV-phase: c-split — warp h owns c in [128h,128h+128) over FULL m;
//           P halves exchanged via 16KB smem stage in 2 passes with
//           pair-local named barriers.  O per warp: 16q x 128c = 64 regs.
// ---------------------------------------------------------------------------
__global__ __launch_bounds__(512, 1)
void attn_kernel(const float* __restrict__ x_main,
                 const float* __restrict__ gamma_p,
                 float* __restrict__ out) {
    extern __shared__ char sm[];
    const uint32_t sb = s2u(sm);
    const int tid = threadIdx.x;
    const int w = tid >> 5, lane = tid & 31;
    const int pair = w >> 1, h = w & 1;
    const int g = lane >> 2, tp = lane & 3;
    const int n0 = blockIdx.x * MT;
    const int b  = blockIdx.y;
    const int q0 = pair * 16;

    const uint32_t a_row = q0 + (lane & 15);
    const uint32_t a_koff = (lane >> 4) * 16;
    const uint32_t b_row7 = lane & 7;
    const uint32_t b_koff = (lane >> 3) * 16;

    // Load Q (one-time)
    {
        const char* qh = (const char*)(g_qh + ((size_t)b * NN + n0) * CI);
        const char* ql = (const char*)(g_ql + ((size_t)b * NN + n0) * CI);
#pragma unroll
        for (int t = 0; t < 4; t++) {
            int e = tid + t * 512;
            int r = e >> 4, c16 = (e & 15) * 16;
            *(uint4*)(sm + SQH + r * RP + c16) = *(const uint4*)(qh + r * 256 + c16);
            *(uint4*)(sm + SQL + r * RP + c16) = *(const uint4*)(ql + r * 256 + c16);
        }
    }
    load_k_chunk(sb, b, 0, tid); CP_COMMIT();
    load_v_chunk(sb, b, 0, tid); CP_COMMIT();
    __syncthreads();

    float o[16][4];
#pragma unroll
    for (int j = 0; j < 16; j++)
#pragma unroll
        for (int i = 0; i < 4; i++) o[j][i] = 0.f;
    float l0 = 0.f, l1 = 0.f;
    uint32_t P[4][4];                 // local k-tiles: global u = 4h + idx

    const uint32_t myslot = sb + SPST + pair * 2048 + h * 1024;
    const uint32_t otslot = sb + SPST + pair * 2048 + (1 - h) * 1024;

    for (int ch = 0; ch < NCH; ch++) {
        CP_WAIT1();            // K[ch] resident (V[ch] may still fly)
        __syncthreads();

        // ===== S = Qh*Kh + Qh*Kl + Ql*Kh  (this warp: m in [64h, 64h+64)) =====
        float s[8][4];
#pragma unroll
        for (int j = 0; j < 8; j++)
#pragma unroll
            for (int i = 0; i < 4; i++) s[j][i] = 0.f;

#pragma unroll
        for (int kk = 0; kk < 4; kk++) {
            uint32_t ah[8], al[8];
            uint32_t ar = sb + SQH + a_row * RP + kk * 64 + a_koff;
            ldsm4(ah, ar); ldsm4(ah + 4, ar + 32);
            uint32_t ar2 = sb + SQL + a_row * RP + kk * 64 + a_koff;
            ldsm4(al, ar2); ldsm4(al + 4, ar2 + 32);
#pragma unroll
            for (int j = 0; j < 8; j++) {
                uint32_t br = (h * 64 + j * 8 + b_row7) * RP + kk * 64 + b_koff;
                uint32_t bh[4], bl[4];
                ldsm4(bh, sb + SKH + br);
                ldsm4(bl, sb + SKL + br);
                mma_bf16(s[j], ah, bh); mma_bf16(s[j], ah + 4, bh + 2);
                mma_bf16(s[j], ah, bl); mma_bf16(s[j], ah + 4, bl + 2);
                mma_bf16(s[j], al, bh); mma_bf16(s[j], al + 4, bh + 2);
            }
        }
        // exp (no max-subtraction) + pack to A-fragments + l accumulation
#pragma unroll
        for (int u = 0; u < 4; u++) {
            float ea0 = __expf(s[2 * u][0]);
            float ea1 = __expf(s[2 * u][1]);
            float ea2 = __expf(s[2 * u][2]);
            float ea3 = __expf(s[2 * u][3]);
            float eb0 = __expf(s[2 * u + 1][0]);
            float eb1 = __expf(s[2 * u + 1][1]);
            float eb2 = __expf(s[2 * u + 1][2]);
            float eb3 = __expf(s[2 * u + 1][3]);
            l0 += (ea0 + ea1) + (eb0 + eb1);
            l1 += (ea2 + ea3) + (eb2 + eb3);
            P[u][0] = pk2(ea1, ea0);
            P[u][1] = pk2(ea3, ea2);
            P[u][2] = pk2(eb1, eb0);
            P[u][3] = pk2(eb3, eb2);
        }
        __syncthreads();                  // everyone done reading K
        if (ch + 1 < NCH) load_k_chunk(sb, b, (ch + 1) * MS, tid);
        CP_COMMIT();

        CP_WAIT1();                       // V[ch] resident (K[ch+1] flying)
        __syncthreads();

        // ===== PV (c-split): warp owns c-half h, full m, 2 exchange passes =====
#pragma unroll
        for (int pass = 0; pass < 2; pass++) {
            // send local P[2*pass], P[2*pass+1]; receive partner's
            sts128(myslot + lane * 16,       P[2 * pass]);
            sts128(myslot + 512 + lane * 16, P[2 * pass + 1]);
            barp(1 + pair);
            uint32_t Pr[8];
            ldsv4(Pr,     otslot + lane * 16);
            ldsv4(Pr + 4, otslot + 512 + lane * 16);
            // blkLow = m-tiles {2p,2p+1} (warp0's local frags)
            // blkHigh = m-tiles {4+2p,4+2p+1} (warp1's local frags)
            const uint32_t* blkLow  = (h == 0) ? &P[2 * pass][0] : Pr;
            const uint32_t* blkHigh = (h == 0) ? Pr : &P[2 * pass][0];
#pragma unroll
            for (int j = 0; j < 16; j++) {
                uint32_t vrow = sb + SVT + (h * 128 + j * 8 + b_row7) * RP + b_koff;
                uint32_t bf[4];
                ldsm4(bf, vrow + pass * 64);
                mma_bf16(o[j], blkLow, bf);
                mma_bf16(o[j], blkLow + 4, bf + 2);
                uint32_t bf2[4];
                ldsm4(bf2, vrow + (pass + 2) * 64);
                mma_bf16(o[j], blkHigh, bf2);
                mma_bf16(o[j], blkHigh + 4, bf2 + 2);
            }
            if (pass == 0) barp(1 + pair);   // partner done reading before overwrite
        }
        __syncthreads();                  // everyone done reading V
        if (ch + 1 < NCH) load_v_chunk(sb, b, (ch + 1) * MS, tid);
        CP_COMMIT();
    }
    CP_WAIT0();

    // l across the 4-thread groups (rows g and g+8 of this warp's m-half)
    l0 += __shfl_xor_sync(0xffffffffu, l0, 1);
    l0 += __shfl_xor_sync(0xffffffffu, l0, 2);
    l1 += __shfl_xor_sync(0xffffffffu, l1, 1);
    l1 += __shfl_xor_sync(0xffffffffu, l1, 2);

    __syncthreads();
    float* lsh = (float*)(sm + SLSH);
    if (tp == 0) {
        lsh[(pair * 2 + h) * 16 + g]     = l0;
        lsh[(pair * 2 + h) * 16 + 8 + g] = l1;
    }
    __syncthreads();
    const float inv0 = 1.0f / (lsh[pair * 32 + g] + lsh[pair * 32 + 16 + g]);
    const float inv1 = 1.0f / (lsh[pair * 32 + 8 + g] + lsh[pair * 32 + 24 + g]);

    // stage this warp's 16q x 128c to smem (conflict-free), then coalesced out
    float* st = (float*)(sm + w * 8704);   // [128 c][17] f32
#pragma unroll
    for (int j = 0; j < 16; j++) {
        int c0 = j * 8 + 2 * tp;
        st[(c0)     * 17 + g]     = o[j][0] * inv0;
        st[(c0 + 1) * 17 + g]     = o[j][1] * inv0;
        st[(c0)     * 17 + g + 8] = o[j][2] * inv1;
        st[(c0 + 1) * 17 + g + 8] = o[j][3] * inv1;
    }
    __syncwarp();
    {
        const float gma = gamma_p[0];
        const int q = lane & 15;
        const int ch2 = lane >> 4;
#pragma unroll 4
        for (int i = 0; i < 64; i++) {
            int cl = i * 2 + ch2;
            int c = h * 128 + cl;
            float v = st[cl * 17 + q];
            size_t gi = ((size_t)b * CC + c) * NN + n0 + q0 + q;
            out[gi] = gma * v + x_main[gi];
        }
    }
}

// ---------------------------------------------------------------------------
extern "C" void kernel_launch(void* const* d_in, const int* in_sizes, int n_in,
                              void* d_out, int out_size) {
    const float* x  = (const float*)d_in[0];
    const float* z  = (const float*)d_in[1];
    const float* Wq = (const float*)d_in[2];
    const float* bq = (const float*)d_in[3];
    const float* Wk = (const float*)d_in[4];
    const float* bk = (const float*)d_in[5];
    const float* Wv = (const float*)d_in[6];
    const float* bv = (const float*)d_in[7];
    const float* ga = (const float*)d_in[8];
    float* out = (float*)d_out;

    cudaFuncSetAttribute(attn_kernel, cudaFuncAttributeMaxDynamicSharedMemorySize,
                         SMEM_TOTAL);

    proj_all_kernel<<<dim3(64, 4, BB), dim3(256)>>>(x, z, Wq, bq, Wk, bk, Wv, bv);
    attn_kernel<<<dim3(NN / MT, BB), dim3(512), SMEM_TOTAL>>>(x, ga, out);
}

// round 12
// speedup vs baseline: 5.0592x; 1.2424x over previous
#include <cuda_runtime.h>
#include <cuda_bf16.h>
#include <cuda_fp16.h>
#include <cstdint>

#define BB 4
#define CC 256
#define CI 128
#define NN 4096
#define MT 128            // q-rows per CTA
#define MS 128            // m chunk
#define NCH (NN / MS)

// Scratch (static __device__)
__device__ __align__(16) __half        g_qf[BB * NN * CI];   // [b][n][ci] fp16
__device__ __align__(16) __half        g_kf[BB * NN * CI];   // [b][m][ci] fp16
__device__ __align__(16) __nv_bfloat16 g_vt[BB * CC * NN];   // [b][c][m]  bf16

// smem byte offsets; row pitch 272B (256B data + 16B pad -> conflict-free ldmatrix)
#define RP    272
#define SQF   0
#define SKF   (SQF + 128 * RP)
#define SVT   (SKF + 128 * RP)
#define SPST  (SVT + 256 * RP)            // P exchange stage: 8 pairs x 2KB = 16KB
#define SLSH  (SPST + 16384)              // l exchange: 256 floats
#define SMEM_TOTAL (SLSH + 1024)          // 156672 B

// ---------------------------------------------------------------------------
// PTX helpers (plain sm_80+ PTX — compiles for sm_103)
// ---------------------------------------------------------------------------
__device__ __forceinline__ uint32_t s2u(const void* p) {
    uint32_t a;
    asm("{ .reg .u64 t; cvta.to.shared.u64 t, %1; cvt.u32.u64 %0, t; }"
        : "=r"(a) : "l"(p));
    return a;
}
__device__ __forceinline__ void ldsm4(uint32_t* r, uint32_t addr) {
    asm volatile("ldmatrix.sync.aligned.m8n8.x4.shared.b16 {%0,%1,%2,%3}, [%4];\n"
                 : "=r"(r[0]), "=r"(r[1]), "=r"(r[2]), "=r"(r[3]) : "r"(addr));
}
__device__ __forceinline__ void mma_bf16(float* c, const uint32_t* a,
                                         const uint32_t* b) {
    asm volatile(
        "mma.sync.aligned.m16n8k16.row.col.f32.bf16.bf16.f32 "
        "{%0,%1,%2,%3}, {%4,%5,%6,%7}, {%8,%9}, {%0,%1,%2,%3};\n"
        : "+f"(c[0]), "+f"(c[1]), "+f"(c[2]), "+f"(c[3])
        : "r"(a[0]), "r"(a[1]), "r"(a[2]), "r"(a[3]), "r"(b[0]), "r"(b[1]));
}
__device__ __forceinline__ void mma_f16(float* c, const uint32_t* a,
                                        const uint32_t* b) {
    asm volatile(
        "mma.sync.aligned.m16n8k16.row.col.f32.f16.f16.f32 "
        "{%0,%1,%2,%3}, {%4,%5,%6,%7}, {%8,%9}, {%0,%1,%2,%3};\n"
        : "+f"(c[0]), "+f"(c[1]), "+f"(c[2]), "+f"(c[3])
        : "r"(a[0]), "r"(a[1]), "r"(a[2]), "r"(a[3]), "r"(b[0]), "r"(b[1]));
}
__device__ __forceinline__ uint32_t pk2(float hi, float lo) {
    uint32_t r;
    asm("cvt.rn.bf16x2.f32 %0, %1, %2;" : "=r"(r) : "f"(hi), "f"(lo));
    return r;
}
__device__ __forceinline__ void cpa16(uint32_t dst, const void* src) {
    asm volatile("cp.async.cg.shared.global [%0], [%1], 16;\n"
                 :: "r"(dst), "l"(src));
}
__device__ __forceinline__ void sts128(uint32_t addr, const uint32_t* v) {
    asm volatile("st.shared.v4.b32 [%0], {%1,%2,%3,%4};\n"
                 :: "r"(addr), "r"(v[0]), "r"(v[1]), "r"(v[2]), "r"(v[3]) : "memory");
}
__device__ __forceinline__ void ldsv4(uint32_t* v, uint32_t addr) {
    asm volatile("ld.shared.v4.b32 {%0,%1,%2,%3}, [%4];\n"
                 : "=r"(v[0]), "=r"(v[1]), "=r"(v[2]), "=r"(v[3]) : "r"(addr));
}
__device__ __forceinline__ void barp(int id) {
    asm volatile("bar.sync %0, 64;\n" :: "r"(id) : "memory");
}
#define CP_COMMIT() asm volatile("cp.async.commit_group;\n" ::: "memory")
#define CP_WAIT1()  asm volatile("cp.async.wait_group 1;\n" ::: "memory")
#define CP_WAIT0()  asm volatile("cp.async.wait_group 0;\n" ::: "memory")

// ---------------------------------------------------------------------------
// Projections: fp32 SIMT compute.
// MODE 0: out fp16 [b][n][O]  (Q, K)      MODE 1: out bf16 [b][o][n] (V^T)
// ---------------------------------------------------------------------------
template <int MODE>
__device__ __forceinline__ void proj_body(const float* __restrict__ in,
                                          const float* __restrict__ W,
                                          const float* __restrict__ bias,
                                          __half* __restrict__ out_h,
                                          __nv_bfloat16* __restrict__ out_bf,
                                          int Cin, int O, int o0) {
    __shared__ float Xs[32 * 64];
    __shared__ float Ws[32 * 132];

    const int tid = threadIdx.x;
    const int ty = tid >> 4;
    const int tx = tid & 15;
    const int n0 = blockIdx.x * 64;
    const int b  = blockIdx.z;
    const float* inb = in + (size_t)b * Cin * NN;

    float acc[4][8];
#pragma unroll
    for (int i = 0; i < 4; i++)
#pragma unroll
        for (int j = 0; j < 8; j++) acc[i][j] = 0.f;

    for (int c0 = 0; c0 < Cin; c0 += 32) {
#pragma unroll
        for (int t = 0; t < 8; t++) {
            int e = tid + t * 256;
            int cc = e >> 6, nn = e & 63;
            Xs[cc * 64 + nn] = inb[(size_t)(c0 + cc) * NN + n0 + nn];
        }
#pragma unroll
        for (int t = 0; t < 16; t++) {
            int e = tid + t * 256;
            int oo = e >> 5, cc = e & 31;
            Ws[cc * 132 + oo] = W[(size_t)(o0 + oo) * Cin + c0 + cc];
        }
        __syncthreads();

#pragma unroll 4
        for (int cc = 0; cc < 32; cc++) {
            float4 w0 = *(const float4*)&Ws[cc * 132 + tx * 4];
            float4 w1 = *(const float4*)&Ws[cc * 132 + 64 + tx * 4];
#pragma unroll
            for (int i = 0; i < 4; i++) {
                float a = Xs[cc * 64 + ty * 4 + i];
                acc[i][0] += a * w0.x; acc[i][1] += a * w0.y;
                acc[i][2] += a * w0.z; acc[i][3] += a * w0.w;
                acc[i][4] += a * w1.x; acc[i][5] += a * w1.y;
                acc[i][6] += a * w1.z; acc[i][7] += a * w1.w;
            }
        }
        __syncthreads();
    }

    float bj[8];
#pragma unroll
    for (int u = 0; u < 4; u++) {
        bj[u]     = bias[o0 + tx * 4 + u];
        bj[4 + u] = bias[o0 + 64 + tx * 4 + u];
    }

    if (MODE == 0) {
#pragma unroll
        for (int i = 0; i < 4; i++) {
            size_t base = ((size_t)b * NN + n0 + ty * 4 + i) * (size_t)O + o0;
#pragma unroll
            for (int hf = 0; hf < 2; hf++) {
                size_t idx = base + hf * 64 + tx * 4;
#pragma unroll
                for (int p = 0; p < 2; p++) {
                    float v0 = acc[i][hf * 4 + 2 * p]     + bj[hf * 4 + 2 * p];
                    float v1 = acc[i][hf * 4 + 2 * p + 1] + bj[hf * 4 + 2 * p + 1];
                    *(__half2*)&out_h[idx + 2 * p] =
                        __floats2half2_rn(v0, v1);
                }
            }
        }
    } else {
#pragma unroll
        for (int hf = 0; hf < 2; hf++)
#pragma unroll
            for (int u = 0; u < 4; u++) {
                int o = o0 + hf * 64 + tx * 4 + u;
                float bb2 = bj[hf * 4 + u];
                size_t base = ((size_t)b * CC + o) * NN + n0 + ty * 4;
                __nv_bfloat16 h0 = __float2bfloat16(acc[0][hf * 4 + u] + bb2);
                __nv_bfloat16 h1 = __float2bfloat16(acc[1][hf * 4 + u] + bb2);
                __nv_bfloat16 h2 = __float2bfloat16(acc[2][hf * 4 + u] + bb2);
                __nv_bfloat16 h3 = __float2bfloat16(acc[3][hf * 4 + u] + bb2);
                *(__nv_bfloat162*)&out_bf[base]     = __halves2bfloat162(h0, h1);
                *(__nv_bfloat162*)&out_bf[base + 2] = __halves2bfloat162(h2, h3);
            }
    }
}

__global__ __launch_bounds__(256) void proj_all_kernel(
    const float* __restrict__ x, const float* __restrict__ z,
    const float* __restrict__ Wq, const float* __restrict__ bq,
    const float* __restrict__ Wk, const float* __restrict__ bk,
    const float* __restrict__ Wv, const float* __restrict__ bv) {
    int sel = blockIdx.y;
    if (sel == 0)
        proj_body<0>(x, Wq, bq, g_qf, nullptr, 256, 128, 0);
    else if (sel == 1)
        proj_body<0>(z, Wk, bk, g_kf, nullptr, 256, 128, 0);
    else
        proj_body<1>(z, Wv, bv, nullptr, g_vt, 256, 256, (sel - 2) * 128);
}

// ---------------------------------------------------------------------------
// cp.async chunk loaders (512 threads)
// ---------------------------------------------------------------------------
__device__ __forceinline__ void load_k_chunk(uint32_t sb, int b, int m0, int tid) {
    const char* kf = (const char*)(g_kf + ((size_t)b * NN + m0) * CI);
#pragma unroll
    for (int t = 0; t < 4; t++) {
        int e = tid + t * 512;
        int r = e >> 4, c16 = (e & 15) * 16;
        cpa16(sb + SKF + r * RP + c16, kf + r * 256 + c16);
    }
}
__device__ __forceinline__ void load_v_chunk(uint32_t sb, int b, int m0, int tid) {
    const char* vt = (const char*)(g_vt + (size_t)b * CC * NN + m0);
#pragma unroll
    for (int t = 0; t < 8; t++) {
        int e = tid + t * 512;
        int r = e >> 4, c16 = (e & 15) * 16;
        cpa16(sb + SVT + r * RP + c16, vt + (size_t)r * (NN * 2) + c16);
    }
}

// ---------------------------------------------------------------------------
// Flash attention, mma.sync. 16 warps = 8 pairs.
// S-phase: single fp16 MMA term (Q,K fp16); warp h covers m-half h.
// PV-phase: c-split, P (bf16) exchanged via smem stage, pair-local barriers.
// ---------------------------------------------------------------------------
__global__ __launch_bounds__(512, 1)
void attn_kernel(const float* __restrict__ x_main,
                 const float* __restrict__ gamma_p,
                 float* __restrict__ out) {
    extern __shared__ char sm[];
    const uint32_t sb = s2u(sm);
    const int tid = threadIdx.x;
    const int w = tid >> 5, lane = tid & 31;
    const int pair = w >> 1, h = w & 1;
    const int g = lane >> 2, tp = lane & 3;
    const int n0 = blockIdx.x * MT;
    const int b  = blockIdx.y;
    const int q0 = pair * 16;

    const uint32_t a_row = q0 + (lane & 15);
    const uint32_t a_koff = (lane >> 4) * 16;
    const uint32_t b_row7 = lane & 7;
    const uint32_t b_koff = (lane >> 3) * 16;

    // Load Q (one-time)
    {
        const char* qf = (const char*)(g_qf + ((size_t)b * NN + n0) * CI);
#pragma unroll
        for (int t = 0; t < 4; t++) {
            int e = tid + t * 512;
            int r = e >> 4, c16 = (e & 15) * 16;
            *(uint4*)(sm + SQF + r * RP + c16) = *(const uint4*)(qf + r * 256 + c16);
        }
    }
    load_k_chunk(sb, b, 0, tid); CP_COMMIT();
    load_v_chunk(sb, b, 0, tid); CP_COMMIT();
    __syncthreads();

    float o[16][4];
#pragma unroll
    for (int j = 0; j < 16; j++)
#pragma unroll
        for (int i = 0; i < 4; i++) o[j][i] = 0.f;
    float l0 = 0.f, l1 = 0.f;
    uint32_t P[4][4];                 // local k-tiles: global u = 4h + idx

    const uint32_t myslot = sb + SPST + pair * 2048 + h * 1024;
    const uint32_t otslot = sb + SPST + pair * 2048 + (1 - h) * 1024;

    for (int ch = 0; ch < NCH; ch++) {
        CP_WAIT1();            // K[ch] resident (V[ch] may still fly)
        __syncthreads();

        // ===== S = Q K^T (single fp16 term; this warp: m in [64h,64h+64)) =====
        float s[8][4];
#pragma unroll
        for (int j = 0; j < 8; j++)
#pragma unroll
            for (int i = 0; i < 4; i++) s[j][i] = 0.f;

#pragma unroll
        for (int kk = 0; kk < 4; kk++) {
            uint32_t a[8];
            uint32_t ar = sb + SQF + a_row * RP + kk * 64 + a_koff;
            ldsm4(a, ar); ldsm4(a + 4, ar + 32);
#pragma unroll
            for (int j = 0; j < 8; j++) {
                uint32_t bf[4];
                ldsm4(bf, sb + SKF + (h * 64 + j * 8 + b_row7) * RP +
                          kk * 64 + b_koff);
                mma_f16(s[j], a, bf);
                mma_f16(s[j], a + 4, bf + 2);
            }
        }
        // exp (no max-subtraction) + pack to bf16 A-fragments + l accumulation
#pragma unroll
        for (int u = 0; u < 4; u++) {
            float ea0 = __expf(s[2 * u][0]);
            float ea1 = __expf(s[2 * u][1]);
            float ea2 = __expf(s[2 * u][2]);
            float ea3 = __expf(s[2 * u][3]);
            float eb0 = __expf(s[2 * u + 1][0]);
            float eb1 = __expf(s[2 * u + 1][1]);
            float eb2 = __expf(s[2 * u + 1][2]);
            float eb3 = __expf(s[2 * u + 1][3]);
            l0 += (ea0 + ea1) + (eb0 + eb1);
            l1 += (ea2 + ea3) + (eb2 + eb3);
            P[u][0] = pk2(ea1, ea0);
            P[u][1] = pk2(ea3, ea2);
            P[u][2] = pk2(eb1, eb0);
            P[u][3] = pk2(eb3, eb2);
        }
        __syncthreads();                  // everyone done reading K
        if (ch + 1 < NCH) load_k_chunk(sb, b, (ch + 1) * MS, tid);
        CP_COMMIT();

        CP_WAIT1();                       // V[ch] resident (K[ch+1] flying)
        __syncthreads();

        // ===== PV (c-split): warp owns c-half h, full m, 2 exchange passes =====
#pragma unroll
        for (int pass = 0; pass < 2; pass++) {
            sts128(myslot + lane * 16,       P[2 * pass]);
            sts128(myslot + 512 + lane * 16, P[2 * pass + 1]);
            barp(1 + pair);
            uint32_t Pr[8];
            ldsv4(Pr,     otslot + lane * 16);
            ldsv4(Pr + 4, otslot + 512 + lane * 16);
            const uint32_t* blkLow  = (h == 0) ? &P[2 * pass][0] : Pr;
            const uint32_t* blkHigh = (h == 0) ? Pr : &P[2 * pass][0];
#pragma unroll
            for (int j = 0; j < 16; j++) {
                uint32_t vrow = sb + SVT + (h * 128 + j * 8 + b_row7) * RP + b_koff;
                uint32_t bf[4];
                ldsm4(bf, vrow + pass * 64);
                mma_bf16(o[j], blkLow, bf);
                mma_bf16(o[j], blkLow + 4, bf + 2);
                uint32_t bf2[4];
                ldsm4(bf2, vrow + (pass + 2) * 64);
                mma_bf16(o[j], blkHigh, bf2);
                mma_bf16(o[j], blkHigh + 4, bf2 + 2);
            }
            if (pass == 0) barp(1 + pair);   // partner done reading before overwrite
        }
        __syncthreads();                  // everyone done reading V
        if (ch + 1 < NCH) load_v_chunk(sb, b, (ch + 1) * MS, tid);
        CP_COMMIT();
    }
    CP_WAIT0();

    // l across the 4-thread groups (rows g and g+8 of this warp's m-half)
    l0 += __shfl_xor_sync(0xffffffffu, l0, 1);
    l0 += __shfl_xor_sync(0xffffffffu, l0, 2);
    l1 += __shfl_xor_sync(0xffffffffu, l1, 1);
    l1 += __shfl_xor_sync(0xffffffffu, l1, 2);

    __syncthreads();
    float* lsh = (float*)(sm + SLSH);
    if (tp == 0) {
        lsh[(pair * 2 + h) * 16 + g]     = l0;
        lsh[(pair * 2 + h) * 16 + 8 + g] = l1;
    }
    __syncthreads();
    const float inv0 = 1.0f / (lsh[pair * 32 + g] + lsh[pair * 32 + 16 + g]);
    const float inv1 = 1.0f / (lsh[pair * 32 + 8 + g] + lsh[pair * 32 + 24 + g]);

    // stage this warp's 16q x 128c to smem (conflict-free), then coalesced out
    float* st = (float*)(sm + w * 8704);   // [128 c][17] f32
#pragma unroll
    for (int j = 0; j < 16; j++) {
        int c0 = j * 8 + 2 * tp;
        st[(c0)     * 17 + g]     = o[j][0] * inv0;
        st[(c0 + 1) * 17 + g]     = o[j][1] * inv0;
        st[(c0)     * 17 + g + 8] = o[j][2] * inv1;
        st[(c0 + 1) * 17 + g + 8] = o[j][3] * inv1;
    }
    __syncwarp();
    {
        const float gma = gamma_p[0];
        const int q = lane & 15;
        const int ch2 = lane >> 4;
#pragma unroll 4
        for (int i = 0; i < 64; i++) {
            int cl = i * 2 + ch2;
            int c = h * 128 + cl;
            float v = st[cl * 17 + q];
            size_t gi = ((size_t)b * CC + c) * NN + n0 + q0 + q;
            out[gi] = gma * v + x_main[gi];
        }
    }
}

// ---------------------------------------------------------------------------
extern "C" void kernel_launch(void* const* d_in, const int* in_sizes, int n_in,
                              void* d_out, int out_size) {
    const float* x  = (const float*)d_in[0];
    const float* z  = (const float*)d_in[1];
    const float* Wq = (const float*)d_in[2];
    const float* bq = (const float*)d_in[3];
    const float* Wk = (const float*)d_in[4];
    const float* bk = (const float*)d_in[5];
    const float* Wv = (const float*)d_in[6];
    const float* bv = (const float*)d_in[7];
    const float* ga = (const float*)d_in[8];
    float* out = (float*)d_out;

    cudaFuncSetAttribute(attn_kernel, cudaFuncAttributeMaxDynamicSharedMemorySize,
                         SMEM_TOTAL);

    proj_all_kernel<<<dim3(64, 4, BB), dim3(256)>>>(x, z, Wq, bq, Wk, bk, Wv, bv);
    attn_kernel<<<dim3(NN / MT, BB), dim3(512), SMEM_TOTAL>>>(x, ga, out);
}

// round 13
// speedup vs baseline: 6.3764x; 1.2604x over previous
#include <cuda_runtime.h>
#include <cuda_bf16.h>
#include <cuda_fp16.h>
#include <cstdint>

#define BB 4
#define CC 256
#define CI 128
#define NN 4096
#define MT 128            // q-rows per CTA
#define MS 128            // m chunk
#define NCH (NN / MS)

// Scratch (static __device__)
__device__ __align__(16) __half        g_qf[BB * NN * CI];   // [b][n][ci] fp16
__device__ __align__(16) __half        g_kf[BB * NN * CI];   // [b][m][ci] fp16
__device__ __align__(16) __nv_bfloat16 g_vt[BB * CC * NN];   // [b][c][m]  bf16

// attn smem; row pitch 272B (256B data + 16B pad -> conflict-free ldmatrix)
#define RP    272
#define SQF   0
#define SKF   (SQF + 128 * RP)
#define SVT   (SKF + 128 * RP)
#define SPST  (SVT + 256 * RP)            // P exchange stage: 8 pairs x 2KB = 16KB
#define SLSH  (SPST + 16384)              // l exchange: 256 floats
#define SMEM_TOTAL (SLSH + 1024)          // 156672 B

// ---------------------------------------------------------------------------
// PTX helpers (plain sm_80+ PTX — compiles for sm_103)
// ---------------------------------------------------------------------------
__device__ __forceinline__ uint32_t s2u(const void* p) {
    uint32_t a;
    asm("{ .reg .u64 t; cvta.to.shared.u64 t, %1; cvt.u32.u64 %0, t; }"
        : "=r"(a) : "l"(p));
    return a;
}
__device__ __forceinline__ void ldsm4(uint32_t* r, uint32_t addr) {
    asm volatile("ldmatrix.sync.aligned.m8n8.x4.shared.b16 {%0,%1,%2,%3}, [%4];\n"
                 : "=r"(r[0]), "=r"(r[1]), "=r"(r[2]), "=r"(r[3]) : "r"(addr));
}
__device__ __forceinline__ void ldsm4t(uint32_t* r, uint32_t addr) {
    asm volatile("ldmatrix.sync.aligned.m8n8.x4.trans.shared.b16 {%0,%1,%2,%3}, [%4];\n"
                 : "=r"(r[0]), "=r"(r[1]), "=r"(r[2]), "=r"(r[3]) : "r"(addr));
}
__device__ __forceinline__ void mma_bf16(float* c, const uint32_t* a,
                                         const uint32_t* b) {
    asm volatile(
        "mma.sync.aligned.m16n8k16.row.col.f32.bf16.bf16.f32 "
        "{%0,%1,%2,%3}, {%4,%5,%6,%7}, {%8,%9}, {%0,%1,%2,%3};\n"
        : "+f"(c[0]), "+f"(c[1]), "+f"(c[2]), "+f"(c[3])
        : "r"(a[0]), "r"(a[1]), "r"(a[2]), "r"(a[3]), "r"(b[0]), "r"(b[1]));
}
__device__ __forceinline__ void mma_f16(float* c, const uint32_t* a,
                                        const uint32_t* b) {
    asm volatile(
        "mma.sync.aligned.m16n8k16.row.col.f32.f16.f16.f32 "
        "{%0,%1,%2,%3}, {%4,%5,%6,%7}, {%8,%9}, {%0,%1,%2,%3};\n"
        : "+f"(c[0]), "+f"(c[1]), "+f"(c[2]), "+f"(c[3])
        : "r"(a[0]), "r"(a[1]), "r"(a[2]), "r"(a[3]), "r"(b[0]), "r"(b[1]));
}
__device__ __forceinline__ uint32_t pk2(float hi, float lo) {
    uint32_t r;
    asm("cvt.rn.bf16x2.f32 %0, %1, %2;" : "=r"(r) : "f"(hi), "f"(lo));
    return r;
}
__device__ __forceinline__ uint32_t f2h2(float a, float b) {
    __half2 h = __floats2half2_rn(a, b);
    return *reinterpret_cast<uint32_t*>(&h);
}
__device__ __forceinline__ void cpa16(uint32_t dst, const void* src) {
    asm volatile("cp.async.cg.shared.global [%0], [%1], 16;\n"
                 :: "r"(dst), "l"(src));
}
__device__ __forceinline__ void sts128(uint32_t addr, const uint32_t* v) {
    asm volatile("st.shared.v4.b32 [%0], {%1,%2,%3,%4};\n"
                 :: "r"(addr), "r"(v[0]), "r"(v[1]), "r"(v[2]), "r"(v[3]) : "memory");
}
__device__ __forceinline__ void ldsv4(uint32_t* v, uint32_t addr) {
    asm volatile("ld.shared.v4.b32 {%0,%1,%2,%3}, [%4];\n"
                 : "=r"(v[0]), "=r"(v[1]), "=r"(v[2]), "=r"(v[3]) : "r"(addr));
}
__device__ __forceinline__ void barp(int id) {
    asm volatile("bar.sync %0, 64;\n" :: "r"(id) : "memory");
}
#define CP_COMMIT() asm volatile("cp.async.commit_group;\n" ::: "memory")
#define CP_WAIT1()  asm volatile("cp.async.wait_group 1;\n" ::: "memory")
#define CP_WAIT0()  asm volatile("cp.async.wait_group 0;\n" ::: "memory")

// ---------------------------------------------------------------------------
// Projections on tensor cores (mma.sync fp16, fp32 accum).
// MODE 0 (Q,K): D[n][o] = trans(in) @ W^T   -> out fp16 [b][n][O]
// MODE 1 (V):   D[o][m] = W @ trans(in)     -> out bf16 [b][o][m]
// CTA tile: 128(n/m) x 128(o), K-loop over 256 c in 4 chunks of 64.
// 8 warps as 2(M) x 4(N); warp tile 64 x 32; D = 64 regs.
// ---------------------------------------------------------------------------
template <int MODE>
__device__ __forceinline__ void proj_mma(const float* __restrict__ in,
                                         const float* __restrict__ W,
                                         const float* __restrict__ bias,
                                         __half* __restrict__ outh,
                                         __nv_bfloat16* __restrict__ outbf,
                                         int o0blk) {
    __shared__ __align__(16) char IN_s[64 * 272];    // [c][128 n] fp16
    __shared__ __align__(16) char W_s[128 * 144];    // [o][64 c]  fp16

    const int tid = threadIdx.x;
    const int w = tid >> 5, lane = tid & 31;
    const int wm = w >> 2, wn = w & 3;
    const int g = lane >> 2, tp = lane & 3;
    const int n0 = blockIdx.x * 128;
    const int b  = blockIdx.z;

    const uint32_t ins = s2u(IN_s), ws = s2u(W_s);

    float d[4][4][4];
#pragma unroll
    for (int i = 0; i < 4; i++)
#pragma unroll
        for (int j = 0; j < 4; j++)
#pragma unroll
            for (int q = 0; q < 4; q++) d[i][j][q] = 0.f;

    for (int ck = 0; ck < 4; ck++) {
        // ---- fill IN chunk: rows c (64), cols n (128), fp32->fp16 ----
        {
            int cl = tid >> 2, cb = (tid & 3) * 32;
            const float* src = in + ((size_t)b * 256 + ck * 64 + cl) * NN + n0 + cb;
            char* dst = IN_s + cl * 272 + cb * 2;
#pragma unroll
            for (int u = 0; u < 8; u++) {
                float4 f = *(const float4*)(src + 4 * u);
                *(uint2*)(dst + 8 * u) = make_uint2(f2h2(f.x, f.y), f2h2(f.z, f.w));
            }
        }
        // ---- fill W chunk: rows o (128), cols c (64), fp32->fp16 ----
        {
            int ol = tid >> 1, cb = (tid & 1) * 32;
            const float* src = W + (size_t)(o0blk + ol) * 256 + ck * 64 + cb;
            char* dst = W_s + ol * 144 + cb * 2;
#pragma unroll
            for (int u = 0; u < 8; u++) {
                float4 f = *(const float4*)(src + 4 * u);
                *(uint2*)(dst + 8 * u) = make_uint2(f2h2(f.x, f.y), f2h2(f.z, f.w));
            }
        }
        __syncthreads();

#pragma unroll
        for (int ks = 0; ks < 2; ks++) {        // two k32 steps per chunk
            uint32_t bfr[4][4];
#pragma unroll
            for (int j = 0; j < 4; j++) {
                if (MODE == 0)
                    ldsm4(bfr[j], ws + (wn * 32 + j * 8 + (lane & 7)) * 144 +
                                   ks * 64 + ((lane >> 3) << 4));
                else
                    ldsm4t(bfr[j], ins + (ks * 32 + (lane & 7) +
                                          ((lane >> 3) << 3)) * 272 +
                                    (wn * 32 + j * 8) * 2);
            }
#pragma unroll
            for (int i = 0; i < 4; i++) {
                uint32_t a0[4], a1[4];
                if (MODE == 0) {
                    uint32_t col = (wm * 64 + i * 16) * 2 + ((lane & 8) << 1);
                    uint32_t kr = ks * 32 + (lane & 7) + ((lane >> 4) << 3);
                    ldsm4t(a0, ins + kr * 272 + col);
                    ldsm4t(a1, ins + (kr + 16) * 272 + col);
                } else {
                    uint32_t ad = ws + (wm * 64 + i * 16 + (lane & 15)) * 144 +
                                  ks * 64 + ((lane >> 4) << 4);
                    ldsm4(a0, ad);
                    ldsm4(a1, ad + 32);
                }
#pragma unroll
                for (int j = 0; j < 4; j++) {
                    mma_f16(d[i][j], a0, bfr[j]);
                    mma_f16(d[i][j], a1, bfr[j] + 2);
                }
            }
        }
        __syncthreads();
    }

    // ---- epilogue with bias ----
    if (MODE == 0) {
#pragma unroll
        for (int j = 0; j < 4; j++) {
            int oc = wn * 32 + j * 8 + 2 * tp;
            float2 bb = *(const float2*)&bias[oc];
#pragma unroll
            for (int i = 0; i < 4; i++) {
                int row = n0 + wm * 64 + i * 16 + g;
                *(uint32_t*)&outh[((size_t)b * NN + row) * CI + oc] =
                    f2h2(d[i][j][0] + bb.x, d[i][j][1] + bb.y);
                *(uint32_t*)&outh[((size_t)b * NN + row + 8) * CI + oc] =
                    f2h2(d[i][j][2] + bb.x, d[i][j][3] + bb.y);
            }
        }
    } else {
#pragma unroll
        for (int i = 0; i < 4; i++) {
            int orow = o0blk + wm * 64 + i * 16 + g;
            float b0 = bias[orow], b8 = bias[orow + 8];
#pragma unroll
            for (int j = 0; j < 4; j++) {
                int mc = n0 + wn * 32 + j * 8 + 2 * tp;
                *(__nv_bfloat162*)&outbf[((size_t)b * CC + orow) * NN + mc] =
                    __floats2bfloat162_rn(d[i][j][0] + b0, d[i][j][1] + b0);
                *(__nv_bfloat162*)&outbf[((size_t)b * CC + orow + 8) * NN + mc] =
                    __floats2bfloat162_rn(d[i][j][2] + b8, d[i][j][3] + b8);
            }
        }
    }
}

__global__ __launch_bounds__(256) void proj_mma_kernel(
    const float* __restrict__ x, const float* __restrict__ z,
    const float* __restrict__ Wq, const float* __restrict__ bq,
    const float* __restrict__ Wk, const float* __restrict__ bk,
    const float* __restrict__ Wv, const float* __restrict__ bv) {
    int sel = blockIdx.y;
    if (sel == 0)
        proj_mma<0>(x, Wq, bq, g_qf, nullptr, 0);
    else if (sel == 1)
        proj_mma<0>(z, Wk, bk, g_kf, nullptr, 0);
    else
        proj_mma<1>(z, Wv, bv, nullptr, g_vt, (sel - 2) * 128);
}

// ---------------------------------------------------------------------------
// cp.async chunk loaders (512 threads)
// ---------------------------------------------------------------------------
__device__ __forceinline__ void load_k_chunk(uint32_t sb, int b, int m0, int tid) {
    const char* kf = (const char*)(g_kf + ((size_t)b * NN + m0) * CI);
#pragma unroll
    for (int t = 0; t < 4; t++) {
        int e = tid + t * 512;
        int r = e >> 4, c16 = (e & 15) * 16;
        cpa16(sb + SKF + r * RP + c16, kf + r * 256 + c16);
    }
}
__device__ __forceinline__ void load_v_chunk(uint32_t sb, int b, int m0, int tid) {
    const char* vt = (const char*)(g_vt + (size_t)b * CC * NN + m0);
#pragma unroll
    for (int t = 0; t < 8; t++) {
        int e = tid + t * 512;
        int r = e >> 4, c16 = (e & 15) * 16;
        cpa16(sb + SVT + r * RP + c16, vt + (size_t)r * (NN * 2) + c16);
    }
}

// ---------------------------------------------------------------------------
// Flash attention, mma.sync. 16 warps = 8 pairs. (proven round-12 core)
// S-phase: single fp16 MMA term (Q,K fp16); warp h covers m-half h.
// PV-phase: c-split, P (bf16) exchanged via smem stage, pair-local barriers.
// ---------------------------------------------------------------------------
__global__ __launch_bounds__(512, 1)
void attn_kernel(const float* __restrict__ x_main,
                 const float* __restrict__ gamma_p,
                 float* __restrict__ out) {
    extern __shared__ char sm[];
    const uint32_t sb = s2u(sm);
    const int tid = threadIdx.x;
    const int w = tid >> 5, lane = tid & 31;
    const int pair = w >> 1, h = w & 1;
    const int g = lane >> 2, tp = lane & 3;
    const int n0 = blockIdx.x * MT;
    const int b  = blockIdx.y;
    const int q0 = pair * 16;

    const uint32_t a_row = q0 + (lane & 15);
    const uint32_t a_koff = (lane >> 4) * 16;
    const uint32_t b_row7 = lane & 7;
    const uint32_t b_koff = (lane >> 3) * 16;

    // Load Q (one-time)
    {
        const char* qf = (const char*)(g_qf + ((size_t)b * NN + n0) * CI);
#pragma unroll
        for (int t = 0; t < 4; t++) {
            int e = tid + t * 512;
            int r = e >> 4, c16 = (e & 15) * 16;
            *(uint4*)(sm + SQF + r * RP + c16) = *(const uint4*)(qf + r * 256 + c16);
        }
    }
    load_k_chunk(sb, b, 0, tid); CP_COMMIT();
    load_v_chunk(sb, b, 0, tid); CP_COMMIT();
    __syncthreads();

    float o[16][4];
#pragma unroll
    for (int j = 0; j < 16; j++)
#pragma unroll
        for (int i = 0; i < 4; i++) o[j][i] = 0.f;
    float l0 = 0.f, l1 = 0.f;
    uint32_t P[4][4];                 // local k-tiles: global u = 4h + idx

    const uint32_t myslot = sb + SPST + pair * 2048 + h * 1024;
    const uint32_t otslot = sb + SPST + pair * 2048 + (1 - h) * 1024;

    for (int ch = 0; ch < NCH; ch++) {
        CP_WAIT1();            // K[ch] resident (V[ch] may still fly)
        __syncthreads();

        // ===== S = Q K^T (single fp16 term; this warp: m in [64h,64h+64)) =====
        float s[8][4];
#pragma unroll
        for (int j = 0; j < 8; j++)
#pragma unroll
            for (int i = 0; i < 4; i++) s[j][i] = 0.f;

#pragma unroll
        for (int kk = 0; kk < 4; kk++) {
            uint32_t a[8];
            uint32_t ar = sb + SQF + a_row * RP + kk * 64 + a_koff;
            ldsm4(a, ar); ldsm4(a + 4, ar + 32);
#pragma unroll
            for (int j = 0; j < 8; j++) {
                uint32_t bf[4];
                ldsm4(bf, sb + SKF + (h * 64 + j * 8 + b_row7) * RP +
                          kk * 64 + b_koff);
                mma_f16(s[j], a, bf);
                mma_f16(s[j], a + 4, bf + 2);
            }
        }
        // exp (no max-subtraction) + pack to bf16 A-fragments + l accumulation
#pragma unroll
        for (int u = 0; u < 4; u++) {
            float ea0 = __expf(s[2 * u][0]);
            float ea1 = __expf(s[2 * u][1]);
            float ea2 = __expf(s[2 * u][2]);
            float ea3 = __expf(s[2 * u][3]);
            float eb0 = __expf(s[2 * u + 1][0]);
            float eb1 = __expf(s[2 * u + 1][1]);
            float eb2 = __expf(s[2 * u + 1][2]);
            float eb3 = __expf(s[2 * u + 1][3]);
            l0 += (ea0 + ea1) + (eb0 + eb1);
            l1 += (ea2 + ea3) + (eb2 + eb3);
            P[u][0] = pk2(ea1, ea0);
            P[u][1] = pk2(ea3, ea2);
            P[u][2] = pk2(eb1, eb0);
            P[u][3] = pk2(eb3, eb2);
        }
        __syncthreads();                  // everyone done reading K
        if (ch + 1 < NCH) load_k_chunk(sb, b, (ch + 1) * MS, tid);
        CP_COMMIT();

        CP_WAIT1();                       // V[ch] resident (K[ch+1] flying)
        __syncthreads();

        // ===== PV (c-split): warp owns c-half h, full m, 2 exchange passes =====
#pragma unroll
        for (int pass = 0; pass < 2; pass++) {
            sts128(myslot + lane * 16,       P[2 * pass]);
            sts128(myslot + 512 + lane * 16, P[2 * pass + 1]);
            barp(1 + pair);
            uint32_t Pr[8];
            ldsv4(Pr,     otslot + lane * 16);
            ldsv4(Pr + 4, otslot + 512 + lane * 16);
            const uint32_t* blkLow  = (h == 0) ? &P[2 * pass][0] : Pr;
            const uint32_t* blkHigh = (h == 0) ? Pr : &P[2 * pass][0];
#pragma unroll
            for (int j = 0; j < 16; j++) {
                uint32_t vrow = sb + SVT + (h * 128 + j * 8 + b_row7) * RP + b_koff;
                uint32_t bf[4];
                ldsm4(bf, vrow + pass * 64);
                mma_bf16(o[j], blkLow, bf);
                mma_bf16(o[j], blkLow + 4, bf + 2);
                uint32_t bf2[4];
                ldsm4(bf2, vrow + (pass + 2) * 64);
                mma_bf16(o[j], blkHigh, bf2);
                mma_bf16(o[j], blkHigh + 4, bf2 + 2);
            }
            if (pass == 0) barp(1 + pair);   // partner done reading before overwrite
        }
        __syncthreads();                  // everyone done reading V
        if (ch + 1 < NCH) load_v_chunk(sb, b, (ch + 1) * MS, tid);
        CP_COMMIT();
    }
    CP_WAIT0();

    // l across the 4-thread groups (rows g and g+8 of this warp's m-half)
    l0 += __shfl_xor_sync(0xffffffffu, l0, 1);
    l0 += __shfl_xor_sync(0xffffffffu, l0, 2);
    l1 += __shfl_xor_sync(0xffffffffu, l1, 1);
    l1 += __shfl_xor_sync(0xffffffffu, l1, 2);

    __syncthreads();
    float* lsh = (float*)(sm + SLSH);
    if (tp == 0) {
        lsh[(pair * 2 + h) * 16 + g]     = l0;
        lsh[(pair * 2 + h) * 16 + 8 + g] = l1;
    }
    __syncthreads();
    const float inv0 = 1.0f / (lsh[pair * 32 + g] + lsh[pair * 32 + 16 + g]);
    const float inv1 = 1.0f / (lsh[pair * 32 + 8 + g] + lsh[pair * 32 + 24 + g]);

    // stage this warp's 16q x 128c to smem (conflict-free), then coalesced out
    float* st = (float*)(sm + w * 8704);   // [128 c][17] f32
#pragma unroll
    for (int j = 0; j < 16; j++) {
        int c0 = j * 8 + 2 * tp;
        st[(c0)     * 17 + g]     = o[j][0] * inv0;
        st[(c0 + 1) * 17 + g]     = o[j][1] * inv0;
        st[(c0)     * 17 + g + 8] = o[j][2] * inv1;
        st[(c0 + 1) * 17 + g + 8] = o[j][3] * inv1;
    }
    __syncwarp();
    {
        const float gma = gamma_p[0];
        const int q = lane & 15;
        const int ch2 = lane >> 4;
#pragma unroll 4
        for (int i = 0; i < 64; i++) {
            int cl = i * 2 + ch2;
            int c = h * 128 + cl;
            float v = st[cl * 17 + q];
            size_t gi = ((size_t)b * CC + c) * NN + n0 + q0 + q;
            out[gi] = gma * v + x_main[gi];
        }
    }
}

// ---------------------------------------------------------------------------
extern "C" void kernel_launch(void* const* d_in, const int* in_sizes, int n_in,
                              void* d_out, int out_size) {
    const float* x  = (const float*)d_in[0];
    const float* z  = (const float*)d_in[1];
    const float* Wq = (const float*)d_in[2];
    const float* bq = (const float*)d_in[3];
    const float* Wk = (const float*)d_in[4];
    const float* bk = (const float*)d_in[5];
    const float* Wv = (const float*)d_in[6];
    const float* bv = (const float*)d_in[7];
    const float* ga = (const float*)d_in[8];
    float* out = (float*)d_out;

    cudaFuncSetAttribute(attn_kernel, cudaFuncAttributeMaxDynamicSharedMemorySize,
                         SMEM_TOTAL);

    proj_mma_kernel<<<dim3(32, 4, BB), dim3(256)>>>(x, z, Wq, bq, Wk, bk, Wv, bv);
    attn_kernel<<<dim3(NN / MT, BB), dim3(512), SMEM_TOTAL>>>(x, ga, out);
}

// round 14
// speedup vs baseline: 7.1131x; 1.1155x over previous
#include <cuda_runtime.h>
#include <cuda_bf16.h>
#include <cuda_fp16.h>
#include <cstdint>

#define BB 4
#define CC 256
#define CI 128
#define NN 4096
#define MT 128            // q-rows per CTA
#define MS 128            // m chunk
#define NCH (NN / MS)
#define L2E 1.4426950408889634f

// Scratch (static __device__)
__device__ __align__(16) __half        g_qf[BB * NN * CI];   // [b][n][ci] fp16 (pre-scaled by log2e)
__device__ __align__(16) __half        g_kf[BB * NN * CI];   // [b][m][ci] fp16
__device__ __align__(16) __nv_bfloat16 g_vt[BB * CC * NN];   // [b][c][m]  bf16

// attn smem; row pitch 272B (256B data + 16B pad -> conflict-free ldmatrix)
#define RP    272
#define SQF   0
#define SKF   (SQF + 128 * RP)            // 34816
#define SVT   (SKF + 128 * RP)            // 69632
#define SPST  (SVT + 256 * RP)            // 139264: P slots, 4 quads x 8KB
#define SLSH  (SPST + 32768)              // 172032: l exchange 16x32 floats
#define SMEM_TOTAL (SLSH + 2048)          // 174080 B

// ---------------------------------------------------------------------------
// PTX helpers (plain sm_80+ PTX — compiles for sm_103)
// ---------------------------------------------------------------------------
__device__ __forceinline__ uint32_t s2u(const void* p) {
    uint32_t a;
    asm("{ .reg .u64 t; cvta.to.shared.u64 t, %1; cvt.u32.u64 %0, t; }"
        : "=r"(a) : "l"(p));
    return a;
}
__device__ __forceinline__ void ldsm4(uint32_t* r, uint32_t addr) {
    asm volatile("ldmatrix.sync.aligned.m8n8.x4.shared.b16 {%0,%1,%2,%3}, [%4];\n"
                 : "=r"(r[0]), "=r"(r[1]), "=r"(r[2]), "=r"(r[3]) : "r"(addr));
}
__device__ __forceinline__ void ldsm4t(uint32_t* r, uint32_t addr) {
    asm volatile("ldmatrix.sync.aligned.m8n8.x4.trans.shared.b16 {%0,%1,%2,%3}, [%4];\n"
                 : "=r"(r[0]), "=r"(r[1]), "=r"(r[2]), "=r"(r[3]) : "r"(addr));
}
__device__ __forceinline__ void mma_bf16(float* c, const uint32_t* a,
                                         const uint32_t* b) {
    asm volatile(
        "mma.sync.aligned.m16n8k16.row.col.f32.bf16.bf16.f32 "
        "{%0,%1,%2,%3}, {%4,%5,%6,%7}, {%8,%9}, {%0,%1,%2,%3};\n"
        : "+f"(c[0]), "+f"(c[1]), "+f"(c[2]), "+f"(c[3])
        : "r"(a[0]), "r"(a[1]), "r"(a[2]), "r"(a[3]), "r"(b[0]), "r"(b[1]));
}
__device__ __forceinline__ void mma_f16(float* c, const uint32_t* a,
                                        const uint32_t* b) {
    asm volatile(
        "mma.sync.aligned.m16n8k16.row.col.f32.f16.f16.f32 "
        "{%0,%1,%2,%3}, {%4,%5,%6,%7}, {%8,%9}, {%0,%1,%2,%3};\n"
        : "+f"(c[0]), "+f"(c[1]), "+f"(c[2]), "+f"(c[3])
        : "r"(a[0]), "r"(a[1]), "r"(a[2]), "r"(a[3]), "r"(b[0]), "r"(b[1]));
}
__device__ __forceinline__ uint32_t pk2(float hi, float lo) {
    uint32_t r;
    asm("cvt.rn.bf16x2.f32 %0, %1, %2;" : "=r"(r) : "f"(hi), "f"(lo));
    return r;
}
__device__ __forceinline__ float ex2(float x) {
    float r;
    asm("ex2.approx.ftz.f32 %0, %1;" : "=f"(r) : "f"(x));
    return r;
}
__device__ __forceinline__ uint32_t f2h2(float a, float b) {
    __half2 h = __floats2half2_rn(a, b);
    return *reinterpret_cast<uint32_t*>(&h);
}
__device__ __forceinline__ void cpa16(uint32_t dst, const void* src) {
    asm volatile("cp.async.cg.shared.global [%0], [%1], 16;\n"
                 :: "r"(dst), "l"(src));
}
__device__ __forceinline__ void sts128(uint32_t addr, const uint32_t* v) {
    asm volatile("st.shared.v4.b32 [%0], {%1,%2,%3,%4};\n"
                 :: "r"(addr), "r"(v[0]), "r"(v[1]), "r"(v[2]), "r"(v[3]) : "memory");
}
__device__ __forceinline__ void ldsv4(uint32_t* v, uint32_t addr) {
    asm volatile("ld.shared.v4.b32 {%0,%1,%2,%3}, [%4];\n"
                 : "=r"(v[0]), "=r"(v[1]), "=r"(v[2]), "=r"(v[3]) : "r"(addr));
}
#define CP_COMMIT() asm volatile("cp.async.commit_group;\n" ::: "memory")
#define CP_WAIT1()  asm volatile("cp.async.wait_group 1;\n" ::: "memory")
#define CP_WAIT0()  asm volatile("cp.async.wait_group 0;\n" ::: "memory")

// ---------------------------------------------------------------------------
// Projections on tensor cores (mma.sync fp16, fp32 accum). (round-13 proven)
// MODE 0 (Q,K): D[n][o] = trans(in) @ W^T  -> fp16 [b][n][O], scaled by sc
// MODE 1 (V):   D[o][m] = W @ trans(in)    -> bf16 [b][o][m]
// ---------------------------------------------------------------------------
template <int MODE>
__device__ __forceinline__ void proj_mma(const float* __restrict__ in,
                                         const float* __restrict__ W,
                                         const float* __restrict__ bias,
                                         __half* __restrict__ outh,
                                         __nv_bfloat16* __restrict__ outbf,
                                         int o0blk, float sc) {
    __shared__ __align__(16) char IN_s[64 * 272];    // [c][128 n] fp16
    __shared__ __align__(16) char W_s[128 * 144];    // [o][64 c]  fp16

    const int tid = threadIdx.x;
    const int w = tid >> 5, lane = tid & 31;
    const int wm = w >> 2, wn = w & 3;
    const int g = lane >> 2, tp = lane & 3;
    const int n0 = blockIdx.x * 128;
    const int b  = blockIdx.z;

    const uint32_t ins = s2u(IN_s), ws = s2u(W_s);

    float d[4][4][4];
#pragma unroll
    for (int i = 0; i < 4; i++)
#pragma unroll
        for (int j = 0; j < 4; j++)
#pragma unroll
            for (int q = 0; q < 4; q++) d[i][j][q] = 0.f;

    for (int ck = 0; ck < 4; ck++) {
        {
            int cl = tid >> 2, cb = (tid & 3) * 32;
            const float* src = in + ((size_t)b * 256 + ck * 64 + cl) * NN + n0 + cb;
            char* dst = IN_s + cl * 272 + cb * 2;
#pragma unroll
            for (int u = 0; u < 8; u++) {
                float4 f = *(const float4*)(src + 4 * u);
                *(uint2*)(dst + 8 * u) = make_uint2(f2h2(f.x, f.y), f2h2(f.z, f.w));
            }
        }
        {
            int ol = tid >> 1, cb = (tid & 1) * 32;
            const float* src = W + (size_t)(o0blk + ol) * 256 + ck * 64 + cb;
            char* dst = W_s + ol * 144 + cb * 2;
#pragma unroll
            for (int u = 0; u < 8; u++) {
                float4 f = *(const float4*)(src + 4 * u);
                *(uint2*)(dst + 8 * u) = make_uint2(f2h2(f.x, f.y), f2h2(f.z, f.w));
            }
        }
        __syncthreads();

#pragma unroll
        for (int ks = 0; ks < 2; ks++) {
            uint32_t bfr[4][4];
#pragma unroll
            for (int j = 0; j < 4; j++) {
                if (MODE == 0)
                    ldsm4(bfr[j], ws + (wn * 32 + j * 8 + (lane & 7)) * 144 +
                                   ks * 64 + ((lane >> 3) << 4));
                else
                    ldsm4t(bfr[j], ins + (ks * 32 + (lane & 7) +
                                          ((lane >> 3) << 3)) * 272 +
                                    (wn * 32 + j * 8) * 2);
            }
#pragma unroll
            for (int i = 0; i < 4; i++) {
                uint32_t a0[4], a1[4];
                if (MODE == 0) {
                    uint32_t col = (wm * 64 + i * 16) * 2 + ((lane & 8) << 1);
                    uint32_t kr = ks * 32 + (lane & 7) + ((lane >> 4) << 3);
                    ldsm4t(a0, ins + kr * 272 + col);
                    ldsm4t(a1, ins + (kr + 16) * 272 + col);
                } else {
                    uint32_t ad = ws + (wm * 64 + i * 16 + (lane & 15)) * 144 +
                                  ks * 64 + ((lane >> 4) << 4);
                    ldsm4(a0, ad);
                    ldsm4(a1, ad + 32);
                }
#pragma unroll
                for (int j = 0; j < 4; j++) {
                    mma_f16(d[i][j], a0, bfr[j]);
                    mma_f16(d[i][j], a1, bfr[j] + 2);
                }
            }
        }
        __syncthreads();
    }

    if (MODE == 0) {
#pragma unroll
        for (int j = 0; j < 4; j++) {
            int oc = wn * 32 + j * 8 + 2 * tp;
            float2 bb = *(const float2*)&bias[oc];
#pragma unroll
            for (int i = 0; i < 4; i++) {
                int row = n0 + wm * 64 + i * 16 + g;
                *(uint32_t*)&outh[((size_t)b * NN + row) * CI + oc] =
                    f2h2((d[i][j][0] + bb.x) * sc, (d[i][j][1] + bb.y) * sc);
                *(uint32_t*)&outh[((size_t)b * NN + row + 8) * CI + oc] =
                    f2h2((d[i][j][2] + bb.x) * sc, (d[i][j][3] + bb.y) * sc);
            }
        }
    } else {
#pragma unroll
        for (int i = 0; i < 4; i++) {
            int orow = o0blk + wm * 64 + i * 16 + g;
            float b0 = bias[orow], b8 = bias[orow + 8];
#pragma unroll
            for (int j = 0; j < 4; j++) {
                int mc = n0 + wn * 32 + j * 8 + 2 * tp;
                *(__nv_bfloat162*)&outbf[((size_t)b * CC + orow) * NN + mc] =
                    __floats2bfloat162_rn(d[i][j][0] + b0, d[i][j][1] + b0);
                *(__nv_bfloat162*)&outbf[((size_t)b * CC + orow + 8) * NN + mc] =
                    __floats2bfloat162_rn(d[i][j][2] + b8, d[i][j][3] + b8);
            }
        }
    }
}

__global__ __launch_bounds__(256) void proj_mma_kernel(
    const float* __restrict__ x, const float* __restrict__ z,
    const float* __restrict__ Wq, const float* __restrict__ bq,
    const float* __restrict__ Wk, const float* __restrict__ bk,
    const float* __restrict__ Wv, const float* __restrict__ bv) {
    int sel = blockIdx.y;
    if (sel == 0)
        proj_mma<0>(x, Wq, bq, g_qf, nullptr, 0, L2E);      // Q pre-scaled
    else if (sel == 1)
        proj_mma<0>(z, Wk, bk, g_kf, nullptr, 0, 1.0f);
    else
        proj_mma<1>(z, Wv, bv, nullptr, g_vt, (sel - 2) * 128, 1.0f);
}

// ---------------------------------------------------------------------------
// cp.async chunk loaders (512 threads)
// ---------------------------------------------------------------------------
__device__ __forceinline__ void load_k_chunk(uint32_t sb, int b, int m0, int tid) {
    const char* kf = (const char*)(g_kf + ((size_t)b * NN + m0) * CI);
#pragma unroll
    for (int t = 0; t < 4; t++) {
        int e = tid + t * 512;
        int r = e >> 4, c16 = (e & 15) * 16;
        cpa16(sb + SKF + r * RP + c16, kf + r * 256 + c16);
    }
}
__device__ __forceinline__ void load_v_chunk(uint32_t sb, int b, int m0, int tid) {
    const char* vt = (const char*)(g_vt + (size_t)b * CC * NN + m0);
#pragma unroll
    for (int t = 0; t < 8; t++) {
        int e = tid + t * 512;
        int r = e >> 4, c16 = (e & 15) * 16;
        cpa16(sb + SVT + r * RP + c16, vt + (size_t)r * (NN * 2) + c16);
    }
}

// ---------------------------------------------------------------------------
// Flash attention, mma.sync. 16 warps = 4 quads; quad owns 32 q-rows.
// S-phase: warp wq covers m-quarter [wq*32, wq*32+32) for its quad's 32 q.
// P exchanged through per-quad smem slots (ordered by existing CTA barriers).
// PV-phase: warp wq owns c-quarter [wq*64, wq*64+64) over FULL m.
// exp2-based softmax (Q pre-scaled by log2e), no max subtraction.
// ---------------------------------------------------------------------------
__global__ __launch_bounds__(512, 1)
void attn_kernel(const float* __restrict__ x_main,
                 const float* __restrict__ gamma_p,
                 float* __restrict__ out) {
    extern __shared__ char sm[];
    const uint32_t sb = s2u(sm);
    const int tid = threadIdx.x;
    const int w = tid >> 5, lane = tid & 31;
    const int quad = w >> 2, wq = w & 3;
    const int g = lane >> 2, tp = lane & 3;
    const int n0 = blockIdx.x * MT;
    const int b  = blockIdx.y;
    const int q0 = quad * 32;

    const uint32_t a_koff = (lane >> 4) * 16;
    const uint32_t brow = lane & 7;
    const uint32_t bk = (lane >> 3) * 16;
    const uint32_t pslot = sb + SPST + quad * 8192;

    // Load Q (one-time)
    {
        const char* qf = (const char*)(g_qf + ((size_t)b * NN + n0) * CI);
#pragma unroll
        for (int t = 0; t < 4; t++) {
            int e = tid + t * 512;
            int r = e >> 4, c16 = (e & 15) * 16;
            *(uint4*)(sm + SQF + r * RP + c16) = *(const uint4*)(qf + r * 256 + c16);
        }
    }
    load_k_chunk(sb, b, 0, tid); CP_COMMIT();
    load_v_chunk(sb, b, 0, tid); CP_COMMIT();
    __syncthreads();

    float o[2][8][4];
#pragma unroll
    for (int i = 0; i < 2; i++)
#pragma unroll
        for (int j = 0; j < 8; j++)
#pragma unroll
            for (int q = 0; q < 4; q++) o[i][j][q] = 0.f;
    float lac[2][2] = {{0.f, 0.f}, {0.f, 0.f}};

    for (int ch = 0; ch < NCH; ch++) {
        CP_WAIT1();            // K[ch] resident (V[ch] may still fly)
        __syncthreads();

        // ===== S = Q K^T (quad's 32 q x this warp's 32 m) =====
        float s[2][4][4];
#pragma unroll
        for (int i = 0; i < 2; i++)
#pragma unroll
            for (int j = 0; j < 4; j++)
#pragma unroll
                for (int q = 0; q < 4; q++) s[i][j][q] = 0.f;

#pragma unroll
        for (int kk = 0; kk < 4; kk++) {
            uint32_t bq_[4][4];
#pragma unroll
            for (int j = 0; j < 4; j++)
                ldsm4(bq_[j], sb + SKF + (wq * 32 + j * 8 + brow) * RP +
                              kk * 64 + bk);
#pragma unroll
            for (int i = 0; i < 2; i++) {
                uint32_t a[8];
                uint32_t ar = sb + SQF + (q0 + i * 16 + (lane & 15)) * RP +
                              kk * 64 + a_koff;
                ldsm4(a, ar); ldsm4(a + 4, ar + 32);
#pragma unroll
                for (int j = 0; j < 4; j++) {
                    mma_f16(s[i][j], a, bq_[j]);
                    mma_f16(s[i][j], a + 4, bq_[j] + 2);
                }
            }
        }

        // exp2 (no max-sub; log2e folded into Q) + l + P -> quad smem slot
#pragma unroll
        for (int i = 0; i < 2; i++)
#pragma unroll
            for (int u = 0; u < 2; u++) {
                float e0 = ex2(s[i][2 * u][0]), e1 = ex2(s[i][2 * u][1]);
                float e2 = ex2(s[i][2 * u][2]), e3 = ex2(s[i][2 * u][3]);
                float f0 = ex2(s[i][2 * u + 1][0]), f1 = ex2(s[i][2 * u + 1][1]);
                float f2 = ex2(s[i][2 * u + 1][2]), f3 = ex2(s[i][2 * u + 1][3]);
                lac[i][0] += (e0 + e1) + (f0 + f1);
                lac[i][1] += (e2 + e3) + (f2 + f3);
                uint32_t Pf[4];
                Pf[0] = pk2(e1, e0);
                Pf[1] = pk2(e3, e2);
                Pf[2] = pk2(f1, f0);
                Pf[3] = pk2(f3, f2);
                sts128(pslot + ((i * 8 + wq * 2 + u) * 32 + lane) * 16, Pf);
            }
        __syncthreads();                  // K consumed + P visible CTA-wide
        if (ch + 1 < NCH) load_k_chunk(sb, b, (ch + 1) * MS, tid);
        CP_COMMIT();

        CP_WAIT1();                       // V[ch] resident (K[ch+1] flying)
        __syncthreads();

        // ===== PV: warp owns c-quarter wq, full 128 m =====
#pragma unroll
        for (int mq = 0; mq < 4; mq++) {
            uint32_t Pr[2][2][4];
#pragma unroll
            for (int i = 0; i < 2; i++)
#pragma unroll
                for (int u = 0; u < 2; u++)
                    ldsv4(Pr[i][u], pslot + ((i * 8 + mq * 2 + u) * 32 + lane) * 16);
#pragma unroll
            for (int j = 0; j < 8; j++) {
                uint32_t bf[4];
                ldsm4(bf, sb + SVT + (wq * 64 + j * 8 + brow) * RP +
                          mq * 64 + bk);
#pragma unroll
                for (int i = 0; i < 2; i++) {
                    mma_bf16(o[i][j], Pr[i][0], bf);
                    mma_bf16(o[i][j], Pr[i][1], bf + 2);
                }
            }
        }
        __syncthreads();                  // V consumed + P reads done
        if (ch + 1 < NCH) load_v_chunk(sb, b, (ch + 1) * MS, tid);
        CP_COMMIT();
    }
    CP_WAIT0();

    // ---- l: reduce across tp lanes, then across the quad via smem ----
    lac[0][0] += __shfl_xor_sync(0xffffffffu, lac[0][0], 1);
    lac[0][0] += __shfl_xor_sync(0xffffffffu, lac[0][0], 2);
    lac[0][1] += __shfl_xor_sync(0xffffffffu, lac[0][1], 1);
    lac[0][1] += __shfl_xor_sync(0xffffffffu, lac[0][1], 2);
    lac[1][0] += __shfl_xor_sync(0xffffffffu, lac[1][0], 1);
    lac[1][0] += __shfl_xor_sync(0xffffffffu, lac[1][0], 2);
    lac[1][1] += __shfl_xor_sync(0xffffffffu, lac[1][1], 1);
    lac[1][1] += __shfl_xor_sync(0xffffffffu, lac[1][1], 2);

    float* lsh = (float*)(sm + SLSH);
    if (tp == 0) {
        lsh[w * 32 + g]          = lac[0][0];
        lsh[w * 32 + 8 + g]      = lac[0][1];
        lsh[w * 32 + 16 + g]     = lac[1][0];
        lsh[w * 32 + 24 + g]     = lac[1][1];
    }
    __syncthreads();
    const float inv = 1.0f / (lsh[(quad * 4 + 0) * 32 + lane] +
                              lsh[(quad * 4 + 1) * 32 + lane] +
                              lsh[(quad * 4 + 2) * 32 + lane] +
                              lsh[(quad * 4 + 3) * 32 + lane]);

    // ---- stage O (64c x 32q, pitch 33) then coalesced epilogue ----
    float* st = (float*)(sm + w * 8448);
#pragma unroll
    for (int i = 0; i < 2; i++)
#pragma unroll
        for (int j = 0; j < 8; j++) {
            int c0 = j * 8 + 2 * tp;
            st[c0 * 33 + i * 16 + g]           = o[i][j][0];
            st[(c0 + 1) * 33 + i * 16 + g]     = o[i][j][1];
            st[c0 * 33 + i * 16 + 8 + g]       = o[i][j][2];
            st[(c0 + 1) * 33 + i * 16 + 8 + g] = o[i][j][3];
        }
    __syncwarp();
    {
        const float gma = gamma_p[0];
#pragma unroll 4
        for (int c = 0; c < 64; c++) {
            int gc = wq * 64 + c;
            size_t gi = ((size_t)b * CC + gc) * NN + n0 + q0 + lane;
            out[gi] = gma * (st[c * 33 + lane] * inv) + x_main[gi];
        }
    }
}

// ---------------------------------------------------------------------------
extern "C" void kernel_launch(void* const* d_in, const int* in_sizes, int n_in,
                              void* d_out, int out_size) {
    const float* x  = (const float*)d_in[0];
    const float* z  = (const float*)d_in[1];
    const float* Wq = (const float*)d_in[2];
    const float* bq = (const float*)d_in[3];
    const float* Wk = (const float*)d_in[4];
    const float* bk = (const float*)d_in[5];
    const float* Wv = (const float*)d_in[6];
    const float* bv = (const float*)d_in[7];
    const float* ga = (const float*)d_in[8];
    float* out = (float*)d_out;

    cudaFuncSetAttribute(attn_kernel, cudaFuncAttributeMaxDynamicSharedMemorySize,
                         SMEM_TOTAL);

    proj_mma_kernel<<<dim3(32, 4, BB), dim3(256)>>>(x, z, Wq, bq, Wk, bk, Wv, bv);
    attn_kernel<<<dim3(NN / MT, BB), dim3(512), SMEM_TOTAL>>>(x, ga, out);
}